// round 1
// baseline (speedup 1.0000x reference)
#include <cuda_runtime.h>
#include <cuda_bf16.h>
#include <cstdio>
#include <cstdint>

// ---------------------------------------------------------------------------
// Model_3D: 3x(conv3d 3x3x3 pad1 + relu + maxpool(2,2,1)) -> mean -> RNN(23) 
//           + linear head.
// Shapes: x (512,6,24,72,3)
//   conv1 -> (512,16,24,72,3) pool -> (512,16,12,36,3)
//   conv2 -> (512,32,12,36,3) pool -> (512,32,6,18,3)
//   conv3 -> (512,64,6,18,3)  pool -> (512,64,3,9,3) stored as (B,D,H,W,C)
//   mean over 81 positions -> (512,64)
//   RNN: 23 steps, hidden 256, 2 layers, pred (512,23,1)
//   head: tanh(flat@W1^T+b) @ W2^T + b -> (512,12)
// Output: [predictions (512*23) | out_c (512*12)] = 17920 floats
// ---------------------------------------------------------------------------

#define B_SZ 512
#define HID 256
#define TLEN 23
#define FLATN 5184

// scratch (device globals: allowed; no cudaMalloc)
__device__ float g_buf1[B_SZ * 16 * 12 * 36 * 3];   // conv1 pooled (NCDHW)
__device__ float g_buf2[B_SZ * 32 * 6 * 18 * 3];    // conv2 pooled (NCDHW)
__device__ float g_buf3[B_SZ * 3 * 9 * 3 * 64];     // conv3 pooled (B,D,H,W,C) == flat
__device__ float g_mean[B_SZ * 64];
__device__ float g_h[B_SZ * HID];
__device__ float g_h2[B_SZ * HID];
__device__ float g_ih[B_SZ * HID];
__device__ float g_t1[B_SZ * HID];

// ---------------------------------------------------------------------------
// Fused conv3d(3x3x3, pad1) + bias + relu + maxpool(2,2,1)
// One block per batch element. Input slab + weight chunk staged in smem.
// Each work item: TOC output channels x PDT pooled-D column at fixed (ph,pw).
// ---------------------------------------------------------------------------
template <int IC, int OC, int D, int H, int W, int OCCHUNK, int TOC, int PDT, bool NDHWC>
__global__ __launch_bounds__(256) void conv_pool_kernel(
    const float* __restrict__ x, const float* __restrict__ wgt,
    const float* __restrict__ bias, float* __restrict__ out)
{
    constexpr int SLAB = IC * D * H * W;
    constexpr int D2 = D / 2, H2 = H / 2;
    constexpr int NDB = D2 / PDT;
    constexpr int WSZ = OCCHUNK * IC * 27;
    constexpr int XC = 2 * PDT + 2;

    extern __shared__ float sm[];
    float* xs = sm;             // SLAB
    float* ws = sm + SLAB;      // WSZ
    float* bs = ws + WSZ;       // OCCHUNK

    const int b = blockIdx.x;
    const int tid = threadIdx.x;
    const int NT = blockDim.x;

    const float* xb = x + (size_t)b * SLAB;
    for (int i = tid; i < SLAB; i += NT) xs[i] = xb[i];

    for (int oc0 = 0; oc0 < OC; oc0 += OCCHUNK) {
        if (oc0 > 0) __syncthreads();   // previous chunk compute done before ws overwrite
        for (int i = tid; i < WSZ; i += NT) ws[i] = wgt[oc0 * IC * 27 + i];
        for (int i = tid; i < OCCHUNK; i += NT) bs[i] = bias[oc0 + i];
        __syncthreads();

        constexpr int NITEMS = (OCCHUNK / TOC) * NDB * H2 * W;
        for (int item = tid; item < NITEMS; item += NT) {
            const int pw = item % W;
            const int ph = (item / W) % H2;
            const int rest = item / (W * H2);
            const int dbi = rest % NDB;
            const int ocb = (rest / NDB) * TOC;
            const int d0 = dbi * PDT * 2;

            float best[TOC][PDT];
#pragma unroll
            for (int a = 0; a < TOC; a++)
#pragma unroll
                for (int p = 0; p < PDT; p++) best[a][p] = -1e30f;

#pragma unroll
            for (int hh = 0; hh < 2; hh++) {
                const int hc = 2 * ph + hh;
                float acc[TOC][2 * PDT];
#pragma unroll
                for (int a = 0; a < TOC; a++)
#pragma unroll
                    for (int dj = 0; dj < 2 * PDT; dj++) acc[a][dj] = 0.f;

                for (int ic = 0; ic < IC; ic++) {
#pragma unroll
                    for (int kh = 0; kh < 3; kh++) {
                        const int hx = hc + kh - 1;
                        if (hx < 0 || hx >= H) continue;
#pragma unroll
                        for (int kw = 0; kw < 3; kw++) {
                            const int wx = pw + kw - 1;
                            if (wx < 0 || wx >= W) continue;
                            const float* xp = &xs[(ic * D * H + hx) * W + wx];
                            float xcol[XC];
#pragma unroll
                            for (int i2 = 0; i2 < XC; i2++) {
                                const int dx = d0 - 1 + i2;
                                xcol[i2] = (dx >= 0 && dx < D) ? xp[dx * H * W] : 0.f;
                            }
#pragma unroll
                            for (int kd = 0; kd < 3; kd++) {
#pragma unroll
                                for (int a = 0; a < TOC; a++) {
                                    const float wv =
                                        ws[((ocb + a) * IC + ic) * 27 + kd * 9 + kh * 3 + kw];
#pragma unroll
                                    for (int dj = 0; dj < 2 * PDT; dj++)
                                        acc[a][dj] += wv * xcol[dj + kd];
                                }
                            }
                        }
                    }
                }
#pragma unroll
                for (int a = 0; a < TOC; a++)
#pragma unroll
                    for (int p = 0; p < PDT; p++) {
                        const float m = fmaxf(acc[a][2 * p], acc[a][2 * p + 1]);
                        best[a][p] = fmaxf(best[a][p], m);
                    }
            }

#pragma unroll
            for (int a = 0; a < TOC; a++) {
                const float bv = bs[ocb + a];
                const int oc = oc0 + ocb + a;
#pragma unroll
                for (int p = 0; p < PDT; p++) {
                    const float v = fmaxf(best[a][p] + bv, 0.f);
                    const int pdg = dbi * PDT + p;
                    size_t o;
                    if constexpr (NDHWC)
                        o = ((((size_t)b * D2 + pdg) * H2 + ph) * W + pw) * OC + oc;
                    else
                        o = ((((size_t)b * OC + oc) * D2 + pdg) * H2 + ph) * W + pw;
                    out[o] = v;
                }
            }
        }
    }
}

// ---------------------------------------------------------------------------
// mean over 81 spatial positions: g_buf3 (B,81,64) -> g_mean (B,64)
// ---------------------------------------------------------------------------
__global__ void mean_kernel() {
    const int b = blockIdx.x, c = threadIdx.x;  // 64 threads
    float s = 0.f;
    const float* p = &g_buf3[(size_t)b * FLATN + c];
    for (int q = 0; q < 81; q++) s += p[q * 64];
    g_mean[b * 64 + c] = s * (1.f / 81.f);
}

// ---------------------------------------------------------------------------
// h = mean @ w_init_h^T + b_init_h ; ih = mean @ wih1^T + bih1 + bhh1
// ---------------------------------------------------------------------------
__global__ __launch_bounds__(256) void init_h_kernel(
    const float* __restrict__ w_init_h, const float* __restrict__ b_init_h,
    const float* __restrict__ wih1, const float* __restrict__ bih1,
    const float* __restrict__ bhh1)
{
    __shared__ float ms[64];
    const int b = blockIdx.x, j = threadIdx.x;
    if (j < 64) ms[j] = g_mean[b * 64 + j];
    __syncthreads();
    float a1 = b_init_h[j];
    float a2 = bih1[j] + bhh1[j];
    const float4* w1r = (const float4*)&w_init_h[(size_t)j * 64];
    const float4* w2r = (const float4*)&wih1[(size_t)j * 64];
    const float4* m4p = (const float4*)ms;
#pragma unroll
    for (int k = 0; k < 16; k++) {
        const float4 m4 = m4p[k];
        const float4 u = w1r[k];
        const float4 v = w2r[k];
        a1 += m4.x * u.x + m4.y * u.y + m4.z * u.z + m4.w * u.w;
        a2 += m4.x * v.x + m4.y * v.y + m4.z * v.z + m4.w * v.w;
    }
    g_h[(size_t)b * HID + j] = a1;
    g_ih[(size_t)b * HID + j] = a2;
}

// h2 = h @ w_init_h2^T + b_init_h2
__global__ __launch_bounds__(256) void init_h2_kernel(
    const float* __restrict__ w_init_h2, const float* __restrict__ b_init_h2)
{
    __shared__ float hs[HID];
    const int b = blockIdx.x, j = threadIdx.x;
    hs[j] = g_h[(size_t)b * HID + j];
    __syncthreads();
    float acc = b_init_h2[j];
    const float4* wr = (const float4*)&w_init_h2[(size_t)j * HID];
    const float4* hp = (const float4*)hs;
#pragma unroll 8
    for (int k = 0; k < HID / 4; k++) {
        const float4 w4 = wr[k];
        const float4 h4 = hp[k];
        acc += h4.x * w4.x + h4.y * w4.y + h4.z * w4.z + h4.w * w4.w;
    }
    g_h2[(size_t)b * HID + j] = acc;
}

// ---------------------------------------------------------------------------
// Entire 23-step RNN in one kernel. Block owns RROWS batch rows (independent
// recurrences). h/h2/ih live in smem; weights streamed from L2 (768KB total).
// ---------------------------------------------------------------------------
#define RROWS 8
__global__ __launch_bounds__(256) void rnn_kernel(
    const float* __restrict__ whh1, const float* __restrict__ wih2,
    const float* __restrict__ whh2, const float* __restrict__ bih2,
    const float* __restrict__ bhh2, const float* __restrict__ w_fc,
    const float* __restrict__ b_fc, float* __restrict__ pred_out)
{
    __shared__ float h_s[RROWS][HID];
    __shared__ float h2_s[RROWS][HID];
    __shared__ float ih_s[RROWS][HID];
    __shared__ float red[8][RROWS];

    const int j = threadIdx.x;
    const int r0 = blockIdx.x * RROWS;
    const int warp = j >> 5, lane = j & 31;

#pragma unroll
    for (int r = 0; r < RROWS; r++) {
        h_s[r][j] = g_h[(size_t)(r0 + r) * HID + j];
        h2_s[r][j] = g_h2[(size_t)(r0 + r) * HID + j];
        ih_s[r][j] = g_ih[(size_t)(r0 + r) * HID + j];
    }
    const float bias2 = bih2[j] + bhh2[j];
    const float wf = w_fc[j];
    const float bfc = b_fc[0];
    __syncthreads();

    const float4* wr1 = (const float4*)&whh1[(size_t)j * HID];
    const float4* wr2 = (const float4*)&wih2[(size_t)j * HID];
    const float4* wr3 = (const float4*)&whh2[(size_t)j * HID];

    for (int t = 0; t < TLEN; t++) {
        // ---- layer 1: h_new = tanh(ih_const + h @ whh1^T) ----
        float hn[RROWS];
#pragma unroll
        for (int r = 0; r < RROWS; r++) hn[r] = ih_s[r][j];
#pragma unroll 4
        for (int k4 = 0; k4 < HID / 4; k4++) {
            const float4 w4 = wr1[k4];
#pragma unroll
            for (int r = 0; r < RROWS; r++) {
                const float4 h4 = ((const float4*)h_s[r])[k4];
                hn[r] += h4.x * w4.x + h4.y * w4.y + h4.z * w4.z + h4.w * w4.w;
            }
        }
#pragma unroll
        for (int r = 0; r < RROWS; r++) hn[r] = tanhf(hn[r]);
        __syncthreads();
#pragma unroll
        for (int r = 0; r < RROWS; r++) h_s[r][j] = hn[r];
        __syncthreads();

        // ---- layer 2: h2_new = tanh(h_new @ wih2^T + h2 @ whh2^T + b) ----
        float h2n[RROWS];
#pragma unroll
        for (int r = 0; r < RROWS; r++) h2n[r] = bias2;
#pragma unroll 4
        for (int k4 = 0; k4 < HID / 4; k4++) {
            const float4 a4 = wr2[k4];
            const float4 b4 = wr3[k4];
#pragma unroll
            for (int r = 0; r < RROWS; r++) {
                const float4 x4 = ((const float4*)h_s[r])[k4];
                const float4 y4 = ((const float4*)h2_s[r])[k4];
                h2n[r] += x4.x * a4.x + x4.y * a4.y + x4.z * a4.z + x4.w * a4.w;
                h2n[r] += y4.x * b4.x + y4.y * b4.y + y4.z * b4.z + y4.w * b4.w;
            }
        }
#pragma unroll
        for (int r = 0; r < RROWS; r++) h2n[r] = tanhf(h2n[r]);
        __syncthreads();
#pragma unroll
        for (int r = 0; r < RROWS; r++) h2_s[r][j] = h2n[r];

        // ---- pred = h2_new @ w_fc^T + b_fc (block-wide reduction) ----
#pragma unroll
        for (int r = 0; r < RROWS; r++) {
            float v = h2n[r] * wf;
            v += __shfl_down_sync(0xffffffffu, v, 16);
            v += __shfl_down_sync(0xffffffffu, v, 8);
            v += __shfl_down_sync(0xffffffffu, v, 4);
            v += __shfl_down_sync(0xffffffffu, v, 2);
            v += __shfl_down_sync(0xffffffffu, v, 1);
            if (lane == 0) red[warp][r] = v;
        }
        __syncthreads();
        if (j < RROWS) {
            float s = bfc;
#pragma unroll
            for (int w = 0; w < 8; w++) s += red[w][j];
            pred_out[(size_t)(r0 + j) * TLEN + t] = s;
        }
        __syncthreads();
    }
}

// ---------------------------------------------------------------------------
// t1 = tanh(flat @ w_lin1^T + b_lin1)   flat = g_buf3 (512, 5184)
// ---------------------------------------------------------------------------
#define L1ROWS 8
#define L1BK 648
__global__ __launch_bounds__(256) void lin1_kernel(
    const float* __restrict__ w_lin1, const float* __restrict__ b_lin1)
{
    __shared__ float fs[L1ROWS * L1BK];
    const int j = threadIdx.x;
    const int r0 = blockIdx.x * L1ROWS;
    float acc[L1ROWS];
#pragma unroll
    for (int r = 0; r < L1ROWS; r++) acc[r] = 0.f;

    for (int kb = 0; kb < FLATN; kb += L1BK) {
        __syncthreads();
        for (int i = j; i < L1ROWS * L1BK; i += 256) {
            const int r = i / L1BK, k = i % L1BK;
            fs[i] = g_buf3[(size_t)(r0 + r) * FLATN + kb + k];
        }
        __syncthreads();
        const float4* wr = (const float4*)&w_lin1[(size_t)j * FLATN + kb];
#pragma unroll 4
        for (int k4 = 0; k4 < L1BK / 4; k4++) {
            const float4 w4 = wr[k4];
#pragma unroll
            for (int r = 0; r < L1ROWS; r++) {
                const float4 f4 = ((const float4*)&fs[r * L1BK])[k4];
                acc[r] += f4.x * w4.x + f4.y * w4.y + f4.z * w4.z + f4.w * w4.w;
            }
        }
    }
    const float bb = b_lin1[j];
#pragma unroll
    for (int r = 0; r < L1ROWS; r++)
        g_t1[(size_t)(r0 + r) * HID + j] = tanhf(acc[r] + bb);
}

// out_c = t1 @ w_lin2^T + b_lin2  (512, 12); warp per (b, m)
__global__ __launch_bounds__(384) void lin2_kernel(
    const float* __restrict__ w_lin2, const float* __restrict__ b_lin2,
    float* __restrict__ outc)
{
    const int b = blockIdx.x;
    const int m = threadIdx.x >> 5;   // 0..11
    const int lane = threadIdx.x & 31;
    const float* tr = &g_t1[(size_t)b * HID];
    const float* wr = &w_lin2[(size_t)m * HID];
    float s = 0.f;
    for (int k = lane; k < HID; k += 32) s += tr[k] * wr[k];
    s += __shfl_down_sync(0xffffffffu, s, 16);
    s += __shfl_down_sync(0xffffffffu, s, 8);
    s += __shfl_down_sync(0xffffffffu, s, 4);
    s += __shfl_down_sync(0xffffffffu, s, 2);
    s += __shfl_down_sync(0xffffffffu, s, 1);
    if (lane == 0) outc[b * 12 + m] = s + b_lin2[m];
}

// ---------------------------------------------------------------------------

extern "C" void kernel_launch(void* const* d_in, const int* in_sizes, int n_in,
                              void* d_out, int out_size)
{
    const float* x        = (const float*)d_in[0];
    const float* w1       = (const float*)d_in[1];
    const float* b1       = (const float*)d_in[2];
    const float* w2       = (const float*)d_in[3];
    const float* b2       = (const float*)d_in[4];
    const float* w3       = (const float*)d_in[5];
    const float* b3       = (const float*)d_in[6];
    const float* wih1     = (const float*)d_in[7];
    const float* whh1     = (const float*)d_in[8];
    const float* bih1     = (const float*)d_in[9];
    const float* bhh1     = (const float*)d_in[10];
    const float* wih2     = (const float*)d_in[11];
    const float* whh2     = (const float*)d_in[12];
    const float* bih2     = (const float*)d_in[13];
    const float* bhh2     = (const float*)d_in[14];
    const float* w_init_h = (const float*)d_in[15];
    const float* b_init_h = (const float*)d_in[16];
    const float* w_init_h2= (const float*)d_in[17];
    const float* b_init_h2= (const float*)d_in[18];
    const float* w_fc     = (const float*)d_in[19];
    const float* b_fc     = (const float*)d_in[20];
    const float* w_lin1   = (const float*)d_in[21];
    const float* b_lin1   = (const float*)d_in[22];
    const float* w_lin2   = (const float*)d_in[23];
    const float* b_lin2   = (const float*)d_in[24];

    float* pred = (float*)d_out;             // 512*23
    float* outc = pred + B_SZ * TLEN;        // 512*12

    float *buf1, *buf2, *buf3;
    cudaGetSymbolAddress((void**)&buf1, g_buf1);
    cudaGetSymbolAddress((void**)&buf2, g_buf2);
    cudaGetSymbolAddress((void**)&buf3, g_buf3);

    // conv stages
    auto k1 = &conv_pool_kernel<6, 16, 24, 72, 3, 16, 4, 6, false>;
    auto k2 = &conv_pool_kernel<16, 32, 12, 36, 3, 32, 4, 6, false>;
    auto k3 = &conv_pool_kernel<32, 64, 6, 18, 3, 32, 4, 3, true>;
    const int sm1 = (6 * 24 * 72 * 3 + 16 * 6 * 27 + 16) * 4;     // 134848
    const int sm2 = (16 * 12 * 36 * 3 + 32 * 16 * 27 + 32) * 4;   // 138368
    const int sm3 = (32 * 6 * 18 * 3 + 32 * 32 * 27 + 32) * 4;    // 152192
    cudaFuncSetAttribute(k1, cudaFuncAttributeMaxDynamicSharedMemorySize, sm1);
    cudaFuncSetAttribute(k2, cudaFuncAttributeMaxDynamicSharedMemorySize, sm2);
    cudaFuncSetAttribute(k3, cudaFuncAttributeMaxDynamicSharedMemorySize, sm3);

    k1<<<B_SZ, 256, sm1>>>(x, w1, b1, buf1);
    k2<<<B_SZ, 256, sm2>>>(buf1, w2, b2, buf2);
    k3<<<B_SZ, 256, sm3>>>(buf2, w3, b3, buf3);

    // encoder mean + RNN init
    mean_kernel<<<B_SZ, 64>>>();
    init_h_kernel<<<B_SZ, 256>>>(w_init_h, b_init_h, wih1, bih1, bhh1);
    init_h2_kernel<<<B_SZ, 256>>>(w_init_h2, b_init_h2);

    // RNN (all 23 steps), 64 blocks of 8 batch rows
    rnn_kernel<<<B_SZ / RROWS, 256>>>(whh1, wih2, whh2, bih2, bhh2, w_fc, b_fc, pred);

    // linear head
    lin1_kernel<<<B_SZ / L1ROWS, 256>>>(w_lin1, b_lin1);
    lin2_kernel<<<B_SZ, 384>>>(w_lin2, b_lin2, outc);

    (void)in_sizes; (void)n_in; (void)out_size;
}

// round 2
// speedup vs baseline: 1.3855x; 1.3855x over previous
#include <cuda_runtime.h>
#include <cuda_bf16.h>
#include <cstdint>

// ---------------------------------------------------------------------------
// Model_3D fused pipeline, f32x2-packed (FFMA2) implementation.
//   pack_weights -> conv1 -> conv2 -> conv3 -> prep -> rnn+lin1 -> lin2
// Output: [predictions (512*23) | out_c (512*12)] = 17920 floats
// ---------------------------------------------------------------------------

#define B_SZ 512
#define HID 256
#define TLEN 23
#define FLATN 5184

typedef unsigned long long ull;

// ---------------- scratch (device globals; no cudaMalloc) -------------------
__device__ float g_buf1[B_SZ * 16 * 12 * 36 * 3];   // conv1 pooled (NCDHW)
__device__ float g_buf2[B_SZ * 32 * 6 * 18 * 3];    // conv2 pooled (NCDHW)
__device__ float g_buf3[B_SZ * 3 * 9 * 3 * 64];     // conv3 pooled (B,D,H,W,C) == flat
__device__ float g_h[B_SZ * HID];
__device__ float g_h2[B_SZ * HID];
__device__ float g_ih[B_SZ * HID];
__device__ float g_t1[B_SZ * HID];

// packed-transposed weights: layout [k4][j] of ulonglong2 (4 consecutive k per j)
__device__ ulonglong2 g_wt[3 * 64 * 256];   // whh1, wih2, whh2 (K=256)
__device__ ulonglong2 g_wAq[16 * 256];      // w_init_h  (K=64)
__device__ ulonglong2 g_wBq[16 * 256];      // wih1      (K=64)
__device__ ulonglong2 g_wCq[64 * 256];      // w_init_h2 (K=256)
__device__ ulonglong2 g_wl1t[1296 * 256];   // w_lin1    (K=5184)

// ---------------- f32x2 helpers --------------------------------------------
__device__ __forceinline__ void fma2(ull& acc, ull a, ull b) {
    asm("fma.rn.f32x2 %0, %1, %2, %0;" : "+l"(acc) : "l"(a), "l"(b));
}
__device__ __forceinline__ ull pk2(float lo, float hi) {
    ull r; asm("mov.b64 %0, {%1,%2};" : "=l"(r) : "f"(lo), "f"(hi)); return r;
}
__device__ __forceinline__ float2 upk(ull v) {
    float lo, hi; asm("mov.b64 {%0,%1}, %2;" : "=f"(lo), "=f"(hi) : "l"(v));
    return make_float2(lo, hi);
}

// ---------------------------------------------------------------------------
// pack_weights: transpose + f32x2-pack all matmul weights into [k4][j] layout.
// idx enumerates destination ulonglong2 elements (j fast).
// ---------------------------------------------------------------------------
__global__ __launch_bounds__(256) void pack_weights_kernel(
    const float* __restrict__ whh1, const float* __restrict__ wih2,
    const float* __restrict__ whh2, const float* __restrict__ w_init_h,
    const float* __restrict__ wih1, const float* __restrict__ w_init_h2,
    const float* __restrict__ w_lin1)
{
    const int idx = blockIdx.x * 256 + threadIdx.x;   // < 405504
    const float* src; ulonglong2* dst; int K; int local;
    if (idx < 49152)      { int m = idx / 16384; local = idx % 16384;
                            src = (m == 0) ? whh1 : ((m == 1) ? wih2 : whh2);
                            dst = g_wt + m * 16384; K = 256; }
    else if (idx < 53248) { local = idx - 49152; src = w_init_h;  dst = g_wAq;  K = 64; }
    else if (idx < 57344) { local = idx - 53248; src = wih1;      dst = g_wBq;  K = 64; }
    else if (idx < 73728) { local = idx - 57344; src = w_init_h2; dst = g_wCq;  K = 256; }
    else                  { local = idx - 73728; src = w_lin1;    dst = g_wl1t; K = 5184; }
    const int j = local % 256;
    const int k4 = local / 256;
    const float4 v = *(const float4*)&src[(size_t)j * K + k4 * 4];
    ulonglong2 o; o.x = pk2(v.x, v.y); o.y = pk2(v.z, v.w);
    dst[local] = o;
}

// ---------------------------------------------------------------------------
// Fused conv3d(3x3x3, pad1) + bias + relu + maxpool(2,2,1), f32x2-packed.
// One block per (batch, oc-chunk). Whole input slab + weight chunk in smem.
// Thread item: TOC ocs x PDT pooled-d x 1 pooled-h x all 3 w.
// Accumulators are f32x2 pairs over adjacent conv-d (the pool pair).
// ---------------------------------------------------------------------------
#define CONVT 288
template <int IC, int OC, int OCG, int D, int H, int TOC, int PDT, bool NDHWC>
__global__ __launch_bounds__(CONVT) void conv_pool2(
    const float* __restrict__ x, const float* __restrict__ wgt,
    const float* __restrict__ bias, float* __restrict__ out)
{
    constexpr int D2 = D / 2, H2 = H / 2;
    constexpr int ND = D2 / PDT;
    constexpr int NOC = OCG / TOC;
    constexpr int SLAB = IC * D * H * 3;
    constexpr int WSZ = OCG * IC * 27;
    constexpr int ITEMS = NOC * ND * H2;
    constexpr int DXC = 2 * PDT + 2;

    extern __shared__ float sm[];
    float* xs = sm;            // SLAB
    float* ws = sm + SLAB;     // WSZ

    const int b = blockIdx.x;
    const int ocbase = blockIdx.y * OCG;
    const int tid = threadIdx.x;

    {   // cooperative loads (all float4-aligned)
        const float4* xb = (const float4*)(x + (size_t)b * SLAB);
        float4* xd = (float4*)xs;
        for (int i = tid; i < SLAB / 4; i += CONVT) xd[i] = xb[i];
        const float4* wb = (const float4*)(wgt + (size_t)ocbase * IC * 27);
        float4* wd = (float4*)ws;
        for (int i = tid; i < WSZ / 4; i += CONVT) wd[i] = wb[i];
    }
    __syncthreads();

    for (int item = tid; item < ITEMS; item += CONVT) {
        const int ph  = item % H2;
        const int rest = item / H2;
        const int pdb = rest % ND;
        const int ocb = (rest / ND) * TOC;
        const int pd0 = pdb * PDT;

        ull acc[TOC][PDT][2][3];
#pragma unroll
        for (int a = 0; a < TOC; a++)
#pragma unroll
            for (int p = 0; p < PDT; p++)
#pragma unroll
                for (int c = 0; c < 2; c++)
#pragma unroll
                    for (int w = 0; w < 3; w++) acc[a][p][c][w] = 0ull;

        for (int ic = 0; ic < IC; ic++) {
            const float* xp = xs + ic * D * H * 3;
#pragma unroll
            for (int hxr = 0; hxr < 4; hxr++) {
                const int hx = 2 * ph - 1 + hxr;
                const bool hok = ((unsigned)hx < (unsigned)H);
                float xr[DXC][3];
#pragma unroll
                for (int i = 0; i < DXC; i++) {
                    const int dx = 2 * pd0 - 1 + i;
                    const bool ok = hok && ((unsigned)dx < (unsigned)D);
                    const float* p = xp + (dx * H + hx) * 3;
                    xr[i][0] = ok ? p[0] : 0.f;
                    xr[i][1] = ok ? p[1] : 0.f;
                    xr[i][2] = ok ? p[2] : 0.f;
                }
                ull xq[DXC - 1][3];
#pragma unroll
                for (int i = 0; i < DXC - 1; i++) {
                    xq[i][0] = pk2(xr[i][0], xr[i + 1][0]);
                    xq[i][1] = pk2(xr[i][1], xr[i + 1][1]);
                    xq[i][2] = pk2(xr[i][2], xr[i + 1][2]);
                }
                // valid (ch, kh) pairs satisfy ch + kh == hxr
#pragma unroll
                for (int ch = 0; ch < 2; ch++) {
                    const int kh = hxr - ch;
                    if (kh < 0 || kh > 2) continue;
#pragma unroll
                    for (int a = 0; a < TOC; a++) {
                        const float* wpa = ws + ((ocb + a) * IC + ic) * 27 + kh * 3;
#pragma unroll
                        for (int kd = 0; kd < 3; kd++) {
                            const float w0 = wpa[kd * 9 + 0];
                            const float w1 = wpa[kd * 9 + 1];
                            const float w2 = wpa[kd * 9 + 2];
                            const ull W0 = pk2(w0, w0), W1 = pk2(w1, w1), W2 = pk2(w2, w2);
#pragma unroll
                            for (int p = 0; p < PDT; p++) {
                                const int xi = 2 * p + kd;
                                fma2(acc[a][p][ch][0], W1, xq[xi][0]);
                                fma2(acc[a][p][ch][0], W2, xq[xi][1]);
                                fma2(acc[a][p][ch][1], W0, xq[xi][0]);
                                fma2(acc[a][p][ch][1], W1, xq[xi][1]);
                                fma2(acc[a][p][ch][1], W2, xq[xi][2]);
                                fma2(acc[a][p][ch][2], W0, xq[xi][1]);
                                fma2(acc[a][p][ch][2], W1, xq[xi][2]);
                            }
                        }
                    }
                }
            }
        }

        // epilogue: pool over (d pair packed halves) x (2 ch), + bias, relu
#pragma unroll
        for (int a = 0; a < TOC; a++) {
            const int oc = ocbase + ocb + a;
            const float bv = __ldg(&bias[oc]);
#pragma unroll
            for (int p = 0; p < PDT; p++) {
                const int pd = pd0 + p;
#pragma unroll
                for (int pw = 0; pw < 3; pw++) {
                    const float2 u0 = upk(acc[a][p][0][pw]);
                    const float2 u1 = upk(acc[a][p][1][pw]);
                    float m = fmaxf(fmaxf(u0.x, u0.y), fmaxf(u1.x, u1.y)) + bv;
                    m = fmaxf(m, 0.f);
                    size_t o;
                    if constexpr (NDHWC)
                        o = ((((size_t)b * D2 + pd) * H2 + ph) * 3 + pw) * OC + oc;
                    else
                        o = (((size_t)b * OC + oc) * D2 + pd) * (H2 * 3) + ph * 3 + pw;
                    out[o] = m;
                }
            }
        }
    }
}

// ---------------------------------------------------------------------------
// prep: mean over 81 positions -> h, ih_const, h2 (one block per batch row)
// ---------------------------------------------------------------------------
__global__ __launch_bounds__(256) void prep_kernel(
    const float* __restrict__ b_init_h, const float* __restrict__ bih1,
    const float* __restrict__ bhh1, const float* __restrict__ b_init_h2)
{
    __shared__ __align__(16) float ms[64];
    __shared__ __align__(16) float hsh[256];
    const int b = blockIdx.x, j = threadIdx.x;
    if (j < 64) {
        float s = 0.f;
        const float* p = g_buf3 + (size_t)b * FLATN + j;
        for (int q = 0; q < 81; q++) s += p[q * 64];
        ms[j] = s * (1.f / 81.f);
    }
    __syncthreads();
    ull aA = 0ull, aB = 0ull;
#pragma unroll
    for (int k4 = 0; k4 < 16; k4++) {
        const ulonglong2 wa = g_wAq[k4 * 256 + j];
        const ulonglong2 wb = g_wBq[k4 * 256 + j];
        const ulonglong2 mv = *(const ulonglong2*)&ms[k4 * 4];
        fma2(aA, wa.x, mv.x); fma2(aA, wa.y, mv.y);
        fma2(aB, wb.x, mv.x); fma2(aB, wb.y, mv.y);
    }
    const float2 uA = upk(aA);
    const float2 uB = upk(aB);
    const float h = uA.x + uA.y + b_init_h[j];
    const float ih = uB.x + uB.y + bih1[j] + bhh1[j];
    g_h[(size_t)b * HID + j] = h;
    g_ih[(size_t)b * HID + j] = ih;
    hsh[j] = h;
    __syncthreads();
    ull aC = 0ull;
#pragma unroll 8
    for (int k4 = 0; k4 < 64; k4++) {
        const ulonglong2 wc = g_wCq[k4 * 256 + j];
        const ulonglong2 hv = *(const ulonglong2*)&hsh[k4 * 4];
        fma2(aC, wc.x, hv.x); fma2(aC, wc.y, hv.y);
    }
    const float2 uC = upk(aC);
    g_h2[(size_t)b * HID + j] = uC.x + uC.y + b_init_h2[j];
}

// ---------------------------------------------------------------------------
// merged: blocks 0..63 run the full 23-step RNN (8 batch rows each);
//         blocks 64..127 run lin1 (tanh(flat @ w_lin1^T + b)) for 8 rows each.
// ---------------------------------------------------------------------------
#define RROWS 8
__global__ __launch_bounds__(256) void rnn_lin1_kernel(
    const float* __restrict__ bih2, const float* __restrict__ bhh2,
    const float* __restrict__ w_fc, const float* __restrict__ b_fc,
    const float* __restrict__ b_lin1, float* __restrict__ pred_out)
{
    __shared__ __align__(16) float sm[6400];
    const int j = threadIdx.x;

    if (blockIdx.x < 64) {
        // ---------------- RNN ----------------
        float* h_s  = sm;           // [8][256]
        float* h2_s = sm + 2048;
        float* ih_s = sm + 4096;
        float* red  = sm + 6144;    // [8 warps][8 rows]
        const int r0 = blockIdx.x * RROWS;
        const int warp = j >> 5, lane = j & 31;
#pragma unroll
        for (int r = 0; r < RROWS; r++) {
            h_s[r * 256 + j]  = g_h[(size_t)(r0 + r) * HID + j];
            h2_s[r * 256 + j] = g_h2[(size_t)(r0 + r) * HID + j];
            ih_s[r * 256 + j] = g_ih[(size_t)(r0 + r) * HID + j];
        }
        const float bias2 = bih2[j] + bhh2[j];
        const float wf = w_fc[j];
        const float bfc = b_fc[0];
        __syncthreads();

        const ulonglong2* W1 = g_wt;
        const ulonglong2* W2 = g_wt + 16384;
        const ulonglong2* W3 = g_wt + 32768;

        for (int t = 0; t < TLEN; t++) {
            ull a1[RROWS];
#pragma unroll
            for (int r = 0; r < RROWS; r++) a1[r] = 0ull;
#pragma unroll 4
            for (int k4 = 0; k4 < 64; k4++) {
                const ulonglong2 wv = W1[k4 * 256 + j];
#pragma unroll
                for (int r = 0; r < RROWS; r++) {
                    const ulonglong2 hv = *(const ulonglong2*)&h_s[r * 256 + k4 * 4];
                    fma2(a1[r], wv.x, hv.x);
                    fma2(a1[r], wv.y, hv.y);
                }
            }
            float hn[RROWS];
#pragma unroll
            for (int r = 0; r < RROWS; r++) {
                const float2 u = upk(a1[r]);
                hn[r] = tanhf(ih_s[r * 256 + j] + u.x + u.y);
            }
            __syncthreads();
#pragma unroll
            for (int r = 0; r < RROWS; r++) h_s[r * 256 + j] = hn[r];
            __syncthreads();

            ull a2[RROWS];
#pragma unroll
            for (int r = 0; r < RROWS; r++) a2[r] = 0ull;
#pragma unroll 2
            for (int k4 = 0; k4 < 64; k4++) {
                const ulonglong2 wv2 = W2[k4 * 256 + j];
                const ulonglong2 wv3 = W3[k4 * 256 + j];
#pragma unroll
                for (int r = 0; r < RROWS; r++) {
                    const ulonglong2 hv = *(const ulonglong2*)&h_s[r * 256 + k4 * 4];
                    const ulonglong2 gv = *(const ulonglong2*)&h2_s[r * 256 + k4 * 4];
                    fma2(a2[r], wv2.x, hv.x);
                    fma2(a2[r], wv2.y, hv.y);
                    fma2(a2[r], wv3.x, gv.x);
                    fma2(a2[r], wv3.y, gv.y);
                }
            }
            float h2n[RROWS];
#pragma unroll
            for (int r = 0; r < RROWS; r++) {
                const float2 u = upk(a2[r]);
                h2n[r] = tanhf(bias2 + u.x + u.y);
            }
            __syncthreads();
#pragma unroll
            for (int r = 0; r < RROWS; r++) h2_s[r * 256 + j] = h2n[r];

#pragma unroll
            for (int r = 0; r < RROWS; r++) {
                float v = h2n[r] * wf;
                v += __shfl_down_sync(0xffffffffu, v, 16);
                v += __shfl_down_sync(0xffffffffu, v, 8);
                v += __shfl_down_sync(0xffffffffu, v, 4);
                v += __shfl_down_sync(0xffffffffu, v, 2);
                v += __shfl_down_sync(0xffffffffu, v, 1);
                if (lane == 0) red[warp * RROWS + r] = v;
            }
            __syncthreads();
            if (j < RROWS) {
                float s = bfc;
#pragma unroll
                for (int w = 0; w < 8; w++) s += red[w * RROWS + j];
                pred_out[(size_t)(r0 + j) * TLEN + t] = s;
            }
            __syncthreads();
        }
    } else {
        // ---------------- lin1 ----------------
        float* fs = sm;    // [8][648]
        const int r0 = (blockIdx.x - 64) * 8;
        ull acc[8];
#pragma unroll
        for (int r = 0; r < 8; r++) acc[r] = 0ull;

        for (int kb = 0; kb < FLATN; kb += 648) {
            __syncthreads();
#pragma unroll
            for (int r = 0; r < 8; r++)
                for (int k = j; k < 648; k += 256)
                    fs[r * 648 + k] = g_buf3[(size_t)(r0 + r) * FLATN + kb + k];
            __syncthreads();
            const int k4b = kb / 4;
#pragma unroll 2
            for (int k4 = 0; k4 < 162; k4++) {
                const ulonglong2 wv = g_wl1t[(k4b + k4) * 256 + j];
#pragma unroll
                for (int r = 0; r < 8; r++) {
                    const ulonglong2 hv = *(const ulonglong2*)&fs[r * 648 + k4 * 4];
                    fma2(acc[r], wv.x, hv.x);
                    fma2(acc[r], wv.y, hv.y);
                }
            }
        }
        const float bb = b_lin1[j];
#pragma unroll
        for (int r = 0; r < 8; r++) {
            const float2 u = upk(acc[r]);
            g_t1[(size_t)(r0 + r) * HID + j] = tanhf(u.x + u.y + bb);
        }
    }
}

// out_c = t1 @ w_lin2^T + b_lin2  (512, 12); warp per (b, m)
__global__ __launch_bounds__(384) void lin2_kernel(
    const float* __restrict__ w_lin2, const float* __restrict__ b_lin2,
    float* __restrict__ outc)
{
    const int b = blockIdx.x;
    const int m = threadIdx.x >> 5;
    const int lane = threadIdx.x & 31;
    const float* tr = &g_t1[(size_t)b * HID];
    const float* wr = &w_lin2[(size_t)m * HID];
    float s = 0.f;
    for (int k = lane; k < HID; k += 32) s += tr[k] * wr[k];
    s += __shfl_down_sync(0xffffffffu, s, 16);
    s += __shfl_down_sync(0xffffffffu, s, 8);
    s += __shfl_down_sync(0xffffffffu, s, 4);
    s += __shfl_down_sync(0xffffffffu, s, 2);
    s += __shfl_down_sync(0xffffffffu, s, 1);
    if (lane == 0) outc[b * 12 + m] = s + b_lin2[m];
}

// ---------------------------------------------------------------------------

extern "C" void kernel_launch(void* const* d_in, const int* in_sizes, int n_in,
                              void* d_out, int out_size)
{
    const float* x        = (const float*)d_in[0];
    const float* w1       = (const float*)d_in[1];
    const float* b1       = (const float*)d_in[2];
    const float* w2       = (const float*)d_in[3];
    const float* b2       = (const float*)d_in[4];
    const float* w3       = (const float*)d_in[5];
    const float* b3       = (const float*)d_in[6];
    const float* wih1     = (const float*)d_in[7];
    const float* whh1     = (const float*)d_in[8];
    const float* bih1     = (const float*)d_in[9];
    const float* bhh1     = (const float*)d_in[10];
    const float* wih2     = (const float*)d_in[11];
    const float* whh2     = (const float*)d_in[12];
    const float* bih2     = (const float*)d_in[13];
    const float* bhh2     = (const float*)d_in[14];
    const float* w_init_h = (const float*)d_in[15];
    const float* b_init_h = (const float*)d_in[16];
    const float* w_init_h2= (const float*)d_in[17];
    const float* b_init_h2= (const float*)d_in[18];
    const float* w_fc     = (const float*)d_in[19];
    const float* b_fc     = (const float*)d_in[20];
    const float* w_lin1   = (const float*)d_in[21];
    const float* b_lin1   = (const float*)d_in[22];
    const float* w_lin2   = (const float*)d_in[23];
    const float* b_lin2   = (const float*)d_in[24];

    float* pred = (float*)d_out;            // 512*23
    float* outc = pred + B_SZ * TLEN;       // 512*12

    float *buf1, *buf2, *buf3;
    cudaGetSymbolAddress((void**)&buf1, g_buf1);
    cudaGetSymbolAddress((void**)&buf2, g_buf2);
    cudaGetSymbolAddress((void**)&buf3, g_buf3);

    // weight pack/transpose first (independent of convs)
    pack_weights_kernel<<<1584, 256>>>(whh1, wih2, whh2, w_init_h, wih1,
                                       w_init_h2, w_lin1);

    auto k1 = &conv_pool2<6, 16, 16, 24, 72, 2, 3, false>;
    auto k2 = &conv_pool2<16, 32, 32, 12, 36, 2, 3, false>;
    auto k3 = &conv_pool2<32, 64, 32, 6, 18, 1, 3, true>;
    const int sm1 = (6 * 24 * 72 * 3 + 16 * 6 * 27) * 4;     // 134784
    const int sm2 = (16 * 12 * 36 * 3 + 32 * 16 * 27) * 4;   // 138240
    const int sm3 = (32 * 6 * 18 * 3 + 32 * 32 * 27) * 4;    // 152064
    cudaFuncSetAttribute(k1, cudaFuncAttributeMaxDynamicSharedMemorySize, sm1);
    cudaFuncSetAttribute(k2, cudaFuncAttributeMaxDynamicSharedMemorySize, sm2);
    cudaFuncSetAttribute(k3, cudaFuncAttributeMaxDynamicSharedMemorySize, sm3);

    k1<<<B_SZ, CONVT, sm1>>>(x, w1, b1, buf1);
    k2<<<B_SZ, CONVT, sm2>>>(buf1, w2, b2, buf2);
    k3<<<dim3(B_SZ, 2), CONVT, sm3>>>(buf2, w3, b3, buf3);

    prep_kernel<<<B_SZ, 256>>>(b_init_h, bih1, bhh1, b_init_h2);

    rnn_lin1_kernel<<<128, 256>>>(bih2, bhh2, w_fc, b_fc, b_lin1, pred);

    lin2_kernel<<<B_SZ, 384>>>(w_lin2, b_lin2, outc);

    (void)in_sizes; (void)n_in; (void)out_size;
}

// round 3
// speedup vs baseline: 1.3871x; 1.0012x over previous
#include <cuda_runtime.h>
#include <cuda_bf16.h>
#include <cstdint>

// ---------------------------------------------------------------------------
// Model_3D fused pipeline, f32x2-packed (FFMA2) implementation.
//   pack_weights -> conv1 -> conv2 -> conv3 -> prep -> rnn+lin1 -> lin2
// Output: [predictions (512*23) | out_c (512*12)] = 17920 floats
// ---------------------------------------------------------------------------

#define B_SZ 512
#define HID 256
#define TLEN 23
#define FLATN 5184

typedef unsigned long long ull;

// ---------------- scratch (device globals; no cudaMalloc) -------------------
__device__ float g_buf1[B_SZ * 16 * 12 * 36 * 3];   // conv1 pooled (NCDHW)
__device__ float g_buf2[B_SZ * 32 * 6 * 18 * 3];    // conv2 pooled (NCDHW)
__device__ float g_buf3[B_SZ * 3 * 9 * 3 * 64];     // conv3 pooled (B,D,H,W,C) == flat
__device__ float g_h[B_SZ * HID];
__device__ float g_h2[B_SZ * HID];
__device__ float g_ih[B_SZ * HID];
__device__ float g_t1[B_SZ * HID];

// packed-transposed weights: layout [k4][j] of ulonglong2 (4 consecutive k per j)
__device__ ulonglong2 g_wt[3 * 64 * 256];   // whh1, wih2, whh2 (K=256)
__device__ ulonglong2 g_wAq[16 * 256];      // w_init_h  (K=64)
__device__ ulonglong2 g_wBq[16 * 256];      // wih1      (K=64)
__device__ ulonglong2 g_wCq[64 * 256];      // w_init_h2 (K=256)
__device__ ulonglong2 g_wl1t[1296 * 256];   // w_lin1    (K=5184)

// ---------------- f32x2 helpers --------------------------------------------
__device__ __forceinline__ void fma2(ull& acc, ull a, ull b) {
    asm("fma.rn.f32x2 %0, %1, %2, %0;" : "+l"(acc) : "l"(a), "l"(b));
}
__device__ __forceinline__ ull pk2(float lo, float hi) {
    ull r; asm("mov.b64 %0, {%1,%2};" : "=l"(r) : "f"(lo), "f"(hi)); return r;
}
__device__ __forceinline__ float2 upk(ull v) {
    float lo, hi; asm("mov.b64 {%0,%1}, %2;" : "=f"(lo), "=f"(hi) : "l"(v));
    return make_float2(lo, hi);
}

// ---------------------------------------------------------------------------
// pack_weights: transpose + f32x2-pack all matmul weights into [k4][j] layout.
// idx enumerates destination ulonglong2 elements (j fast).
// ---------------------------------------------------------------------------
__global__ __launch_bounds__(256) void pack_weights_kernel(
    const float* __restrict__ whh1, const float* __restrict__ wih2,
    const float* __restrict__ whh2, const float* __restrict__ w_init_h,
    const float* __restrict__ wih1, const float* __restrict__ w_init_h2,
    const float* __restrict__ w_lin1)
{
    const int idx = blockIdx.x * 256 + threadIdx.x;   // < 405504
    const float* src; ulonglong2* dst; int K; int local;
    if (idx < 49152)      { int m = idx / 16384; local = idx % 16384;
                            src = (m == 0) ? whh1 : ((m == 1) ? wih2 : whh2);
                            dst = g_wt + m * 16384; K = 256; }
    else if (idx < 53248) { local = idx - 49152; src = w_init_h;  dst = g_wAq;  K = 64; }
    else if (idx < 57344) { local = idx - 53248; src = wih1;      dst = g_wBq;  K = 64; }
    else if (idx < 73728) { local = idx - 57344; src = w_init_h2; dst = g_wCq;  K = 256; }
    else                  { local = idx - 73728; src = w_lin1;    dst = g_wl1t; K = 5184; }
    const int j = local % 256;
    const int k4 = local / 256;
    const float4 v = *(const float4*)&src[(size_t)j * K + k4 * 4];
    ulonglong2 o; o.x = pk2(v.x, v.y); o.y = pk2(v.z, v.w);
    dst[local] = o;
}

// ---------------------------------------------------------------------------
// Fused conv3d(3x3x3, pad1) + bias + relu + maxpool(2,2,1), f32x2-packed.
// One block per (batch, oc-chunk). Whole input slab + weight chunk in smem.
// Thread item: TOC ocs x PDT pooled-d x 1 pooled-h x all 3 w.
// Accumulators are f32x2 pairs over adjacent conv-d (the pool pair).
// ---------------------------------------------------------------------------
#define CONVT 288
template <int IC, int OC, int OCG, int D, int H, int TOC, int PDT, bool NDHWC>
__global__ __launch_bounds__(CONVT) void conv_pool2(
    const float* __restrict__ x, const float* __restrict__ wgt,
    const float* __restrict__ bias, float* __restrict__ out)
{
    constexpr int D2 = D / 2, H2 = H / 2;
    constexpr int ND = D2 / PDT;
    constexpr int NOC = OCG / TOC;
    constexpr int SLAB = IC * D * H * 3;
    constexpr int WSZ = OCG * IC * 27;
    constexpr int ITEMS = NOC * ND * H2;
    constexpr int DXC = 2 * PDT + 2;

    extern __shared__ float sm[];
    float* xs = sm;            // SLAB
    float* ws = sm + SLAB;     // WSZ

    const int b = blockIdx.x;
    const int ocbase = blockIdx.y * OCG;
    const int tid = threadIdx.x;

    {   // cooperative loads (all float4-aligned)
        const float4* xb = (const float4*)(x + (size_t)b * SLAB);
        float4* xd = (float4*)xs;
        for (int i = tid; i < SLAB / 4; i += CONVT) xd[i] = xb[i];
        const float4* wb = (const float4*)(wgt + (size_t)ocbase * IC * 27);
        float4* wd = (float4*)ws;
        for (int i = tid; i < WSZ / 4; i += CONVT) wd[i] = wb[i];
    }
    __syncthreads();

    for (int item = tid; item < ITEMS; item += CONVT) {
        const int ph  = item % H2;
        const int rest = item / H2;
        const int pdb = rest % ND;
        const int ocb = (rest / ND) * TOC;
        const int pd0 = pdb * PDT;

        ull acc[TOC][PDT][2][3];
#pragma unroll
        for (int a = 0; a < TOC; a++)
#pragma unroll
            for (int p = 0; p < PDT; p++)
#pragma unroll
                for (int c = 0; c < 2; c++)
#pragma unroll
                    for (int w = 0; w < 3; w++) acc[a][p][c][w] = 0ull;

        for (int ic = 0; ic < IC; ic++) {
            const float* xp = xs + ic * D * H * 3;
#pragma unroll
            for (int hxr = 0; hxr < 4; hxr++) {
                const int hx = 2 * ph - 1 + hxr;
                const bool hok = ((unsigned)hx < (unsigned)H);
                float xr[DXC][3];
#pragma unroll
                for (int i = 0; i < DXC; i++) {
                    const int dx = 2 * pd0 - 1 + i;
                    const bool ok = hok && ((unsigned)dx < (unsigned)D);
                    const float* p = xp + (dx * H + hx) * 3;
                    xr[i][0] = ok ? p[0] : 0.f;
                    xr[i][1] = ok ? p[1] : 0.f;
                    xr[i][2] = ok ? p[2] : 0.f;
                }
                ull xq[DXC - 1][3];
#pragma unroll
                for (int i = 0; i < DXC - 1; i++) {
                    xq[i][0] = pk2(xr[i][0], xr[i + 1][0]);
                    xq[i][1] = pk2(xr[i][1], xr[i + 1][1]);
                    xq[i][2] = pk2(xr[i][2], xr[i + 1][2]);
                }
                // valid (ch, kh) pairs satisfy ch + kh == hxr
#pragma unroll
                for (int ch = 0; ch < 2; ch++) {
                    const int kh = hxr - ch;
                    if (kh < 0 || kh > 2) continue;
#pragma unroll
                    for (int a = 0; a < TOC; a++) {
                        const float* wpa = ws + ((ocb + a) * IC + ic) * 27 + kh * 3;
#pragma unroll
                        for (int kd = 0; kd < 3; kd++) {
                            const float w0 = wpa[kd * 9 + 0];
                            const float w1 = wpa[kd * 9 + 1];
                            const float w2 = wpa[kd * 9 + 2];
                            const ull W0 = pk2(w0, w0), W1 = pk2(w1, w1), W2 = pk2(w2, w2);
#pragma unroll
                            for (int p = 0; p < PDT; p++) {
                                const int xi = 2 * p + kd;
                                fma2(acc[a][p][ch][0], W1, xq[xi][0]);
                                fma2(acc[a][p][ch][0], W2, xq[xi][1]);
                                fma2(acc[a][p][ch][1], W0, xq[xi][0]);
                                fma2(acc[a][p][ch][1], W1, xq[xi][1]);
                                fma2(acc[a][p][ch][1], W2, xq[xi][2]);
                                fma2(acc[a][p][ch][2], W0, xq[xi][1]);
                                fma2(acc[a][p][ch][2], W1, xq[xi][2]);
                            }
                        }
                    }
                }
            }
        }

        // epilogue: pool over (d pair packed halves) x (2 ch), + bias, relu
#pragma unroll
        for (int a = 0; a < TOC; a++) {
            const int oc = ocbase + ocb + a;
            const float bv = __ldg(&bias[oc]);
#pragma unroll
            for (int p = 0; p < PDT; p++) {
                const int pd = pd0 + p;
#pragma unroll
                for (int pw = 0; pw < 3; pw++) {
                    const float2 u0 = upk(acc[a][p][0][pw]);
                    const float2 u1 = upk(acc[a][p][1][pw]);
                    float m = fmaxf(fmaxf(u0.x, u0.y), fmaxf(u1.x, u1.y)) + bv;
                    m = fmaxf(m, 0.f);
                    size_t o;
                    if constexpr (NDHWC)
                        o = ((((size_t)b * D2 + pd) * H2 + ph) * 3 + pw) * OC + oc;
                    else
                        o = (((size_t)b * OC + oc) * D2 + pd) * (H2 * 3) + ph * 3 + pw;
                    out[o] = m;
                }
            }
        }
    }
}

// ---------------------------------------------------------------------------
// prep: mean over 81 positions -> h, ih_const, h2 (one block per batch row)
// ---------------------------------------------------------------------------
__global__ __launch_bounds__(256) void prep_kernel(
    const float* __restrict__ b_init_h, const float* __restrict__ bih1,
    const float* __restrict__ bhh1, const float* __restrict__ b_init_h2)
{
    __shared__ __align__(16) float ms[64];
    __shared__ __align__(16) float hsh[256];
    const int b = blockIdx.x, j = threadIdx.x;
    if (j < 64) {
        float s = 0.f;
        const float* p = g_buf3 + (size_t)b * FLATN + j;
        for (int q = 0; q < 81; q++) s += p[q * 64];
        ms[j] = s * (1.f / 81.f);
    }
    __syncthreads();
    ull aA = 0ull, aB = 0ull;
#pragma unroll
    for (int k4 = 0; k4 < 16; k4++) {
        const ulonglong2 wa = g_wAq[k4 * 256 + j];
        const ulonglong2 wb = g_wBq[k4 * 256 + j];
        const ulonglong2 mv = *(const ulonglong2*)&ms[k4 * 4];
        fma2(aA, wa.x, mv.x); fma2(aA, wa.y, mv.y);
        fma2(aB, wb.x, mv.x); fma2(aB, wb.y, mv.y);
    }
    const float2 uA = upk(aA);
    const float2 uB = upk(aB);
    const float h = uA.x + uA.y + b_init_h[j];
    const float ih = uB.x + uB.y + bih1[j] + bhh1[j];
    g_h[(size_t)b * HID + j] = h;
    g_ih[(size_t)b * HID + j] = ih;
    hsh[j] = h;
    __syncthreads();
    ull aC = 0ull;
#pragma unroll 8
    for (int k4 = 0; k4 < 64; k4++) {
        const ulonglong2 wc = g_wCq[k4 * 256 + j];
        const ulonglong2 hv = *(const ulonglong2*)&hsh[k4 * 4];
        fma2(aC, wc.x, hv.x); fma2(aC, wc.y, hv.y);
    }
    const float2 uC = upk(aC);
    g_h2[(size_t)b * HID + j] = uC.x + uC.y + b_init_h2[j];
}

// ---------------------------------------------------------------------------
// merged: blocks 0..63 run the full 23-step RNN (8 batch rows each);
//         blocks 64..127 run lin1 (tanh(flat @ w_lin1^T + b)) for 8 rows each.
// ---------------------------------------------------------------------------
#define RROWS 8
__global__ __launch_bounds__(256) void rnn_lin1_kernel(
    const float* __restrict__ bih2, const float* __restrict__ bhh2,
    const float* __restrict__ w_fc, const float* __restrict__ b_fc,
    const float* __restrict__ b_lin1, float* __restrict__ pred_out)
{
    __shared__ __align__(16) float sm[6400];
    const int j = threadIdx.x;

    if (blockIdx.x < 64) {
        // ---------------- RNN ----------------
        float* h_s  = sm;           // [8][256]
        float* h2_s = sm + 2048;
        float* ih_s = sm + 4096;
        float* red  = sm + 6144;    // [8 warps][8 rows]
        const int r0 = blockIdx.x * RROWS;
        const int warp = j >> 5, lane = j & 31;
#pragma unroll
        for (int r = 0; r < RROWS; r++) {
            h_s[r * 256 + j]  = g_h[(size_t)(r0 + r) * HID + j];
            h2_s[r * 256 + j] = g_h2[(size_t)(r0 + r) * HID + j];
            ih_s[r * 256 + j] = g_ih[(size_t)(r0 + r) * HID + j];
        }
        const float bias2 = bih2[j] + bhh2[j];
        const float wf = w_fc[j];
        const float bfc = b_fc[0];
        __syncthreads();

        const ulonglong2* W1 = g_wt;
        const ulonglong2* W2 = g_wt + 16384;
        const ulonglong2* W3 = g_wt + 32768;

        for (int t = 0; t < TLEN; t++) {
            ull a1[RROWS];
#pragma unroll
            for (int r = 0; r < RROWS; r++) a1[r] = 0ull;
#pragma unroll 4
            for (int k4 = 0; k4 < 64; k4++) {
                const ulonglong2 wv = W1[k4 * 256 + j];
#pragma unroll
                for (int r = 0; r < RROWS; r++) {
                    const ulonglong2 hv = *(const ulonglong2*)&h_s[r * 256 + k4 * 4];
                    fma2(a1[r], wv.x, hv.x);
                    fma2(a1[r], wv.y, hv.y);
                }
            }
            float hn[RROWS];
#pragma unroll
            for (int r = 0; r < RROWS; r++) {
                const float2 u = upk(a1[r]);
                hn[r] = tanhf(ih_s[r * 256 + j] + u.x + u.y);
            }
            __syncthreads();
#pragma unroll
            for (int r = 0; r < RROWS; r++) h_s[r * 256 + j] = hn[r];
            __syncthreads();

            ull a2[RROWS];
#pragma unroll
            for (int r = 0; r < RROWS; r++) a2[r] = 0ull;
#pragma unroll 2
            for (int k4 = 0; k4 < 64; k4++) {
                const ulonglong2 wv2 = W2[k4 * 256 + j];
                const ulonglong2 wv3 = W3[k4 * 256 + j];
#pragma unroll
                for (int r = 0; r < RROWS; r++) {
                    const ulonglong2 hv = *(const ulonglong2*)&h_s[r * 256 + k4 * 4];
                    const ulonglong2 gv = *(const ulonglong2*)&h2_s[r * 256 + k4 * 4];
                    fma2(a2[r], wv2.x, hv.x);
                    fma2(a2[r], wv2.y, hv.y);
                    fma2(a2[r], wv3.x, gv.x);
                    fma2(a2[r], wv3.y, gv.y);
                }
            }
            float h2n[RROWS];
#pragma unroll
            for (int r = 0; r < RROWS; r++) {
                const float2 u = upk(a2[r]);
                h2n[r] = tanhf(bias2 + u.x + u.y);
            }
            __syncthreads();
#pragma unroll
            for (int r = 0; r < RROWS; r++) h2_s[r * 256 + j] = h2n[r];

#pragma unroll
            for (int r = 0; r < RROWS; r++) {
                float v = h2n[r] * wf;
                v += __shfl_down_sync(0xffffffffu, v, 16);
                v += __shfl_down_sync(0xffffffffu, v, 8);
                v += __shfl_down_sync(0xffffffffu, v, 4);
                v += __shfl_down_sync(0xffffffffu, v, 2);
                v += __shfl_down_sync(0xffffffffu, v, 1);
                if (lane == 0) red[warp * RROWS + r] = v;
            }
            __syncthreads();
            if (j < RROWS) {
                float s = bfc;
#pragma unroll
                for (int w = 0; w < 8; w++) s += red[w * RROWS + j];
                pred_out[(size_t)(r0 + j) * TLEN + t] = s;
            }
            __syncthreads();
        }
    } else {
        // ---------------- lin1 ----------------
        float* fs = sm;    // [8][648]
        const int r0 = (blockIdx.x - 64) * 8;
        ull acc[8];
#pragma unroll
        for (int r = 0; r < 8; r++) acc[r] = 0ull;

        for (int kb = 0; kb < FLATN; kb += 648) {
            __syncthreads();
#pragma unroll
            for (int r = 0; r < 8; r++)
                for (int k = j; k < 648; k += 256)
                    fs[r * 648 + k] = g_buf3[(size_t)(r0 + r) * FLATN + kb + k];
            __syncthreads();
            const int k4b = kb / 4;
#pragma unroll 2
            for (int k4 = 0; k4 < 162; k4++) {
                const ulonglong2 wv = g_wl1t[(k4b + k4) * 256 + j];
#pragma unroll
                for (int r = 0; r < 8; r++) {
                    const ulonglong2 hv = *(const ulonglong2*)&fs[r * 648 + k4 * 4];
                    fma2(acc[r], wv.x, hv.x);
                    fma2(acc[r], wv.y, hv.y);
                }
            }
        }
        const float bb = b_lin1[j];
#pragma unroll
        for (int r = 0; r < 8; r++) {
            const float2 u = upk(acc[r]);
            g_t1[(size_t)(r0 + r) * HID + j] = tanhf(u.x + u.y + bb);
        }
    }
}

// out_c = t1 @ w_lin2^T + b_lin2  (512, 12); warp per (b, m)
__global__ __launch_bounds__(384) void lin2_kernel(
    const float* __restrict__ w_lin2, const float* __restrict__ b_lin2,
    float* __restrict__ outc)
{
    const int b = blockIdx.x;
    const int m = threadIdx.x >> 5;
    const int lane = threadIdx.x & 31;
    const float* tr = &g_t1[(size_t)b * HID];
    const float* wr = &w_lin2[(size_t)m * HID];
    float s = 0.f;
    for (int k = lane; k < HID; k += 32) s += tr[k] * wr[k];
    s += __shfl_down_sync(0xffffffffu, s, 16);
    s += __shfl_down_sync(0xffffffffu, s, 8);
    s += __shfl_down_sync(0xffffffffu, s, 4);
    s += __shfl_down_sync(0xffffffffu, s, 2);
    s += __shfl_down_sync(0xffffffffu, s, 1);
    if (lane == 0) outc[b * 12 + m] = s + b_lin2[m];
}

// ---------------------------------------------------------------------------

extern "C" void kernel_launch(void* const* d_in, const int* in_sizes, int n_in,
                              void* d_out, int out_size)
{
    const float* x        = (const float*)d_in[0];
    const float* w1       = (const float*)d_in[1];
    const float* b1       = (const float*)d_in[2];
    const float* w2       = (const float*)d_in[3];
    const float* b2       = (const float*)d_in[4];
    const float* w3       = (const float*)d_in[5];
    const float* b3       = (const float*)d_in[6];
    const float* wih1     = (const float*)d_in[7];
    const float* whh1     = (const float*)d_in[8];
    const float* bih1     = (const float*)d_in[9];
    const float* bhh1     = (const float*)d_in[10];
    const float* wih2     = (const float*)d_in[11];
    const float* whh2     = (const float*)d_in[12];
    const float* bih2     = (const float*)d_in[13];
    const float* bhh2     = (const float*)d_in[14];
    const float* w_init_h = (const float*)d_in[15];
    const float* b_init_h = (const float*)d_in[16];
    const float* w_init_h2= (const float*)d_in[17];
    const float* b_init_h2= (const float*)d_in[18];
    const float* w_fc     = (const float*)d_in[19];
    const float* b_fc     = (const float*)d_in[20];
    const float* w_lin1   = (const float*)d_in[21];
    const float* b_lin1   = (const float*)d_in[22];
    const float* w_lin2   = (const float*)d_in[23];
    const float* b_lin2   = (const float*)d_in[24];

    float* pred = (float*)d_out;            // 512*23
    float* outc = pred + B_SZ * TLEN;       // 512*12

    float *buf1, *buf2, *buf3;
    cudaGetSymbolAddress((void**)&buf1, g_buf1);
    cudaGetSymbolAddress((void**)&buf2, g_buf2);
    cudaGetSymbolAddress((void**)&buf3, g_buf3);

    // weight pack/transpose first (independent of convs)
    pack_weights_kernel<<<1584, 256>>>(whh1, wih2, whh2, w_init_h, wih1,
                                       w_init_h2, w_lin1);

    auto k1 = &conv_pool2<6, 16, 16, 24, 72, 2, 3, false>;
    auto k2 = &conv_pool2<16, 32, 32, 12, 36, 2, 3, false>;
    auto k3 = &conv_pool2<32, 64, 32, 6, 18, 1, 3, true>;
    const int sm1 = (6 * 24 * 72 * 3 + 16 * 6 * 27) * 4;     // 134784
    const int sm2 = (16 * 12 * 36 * 3 + 32 * 16 * 27) * 4;   // 138240
    const int sm3 = (32 * 6 * 18 * 3 + 32 * 32 * 27) * 4;    // 152064
    cudaFuncSetAttribute(k1, cudaFuncAttributeMaxDynamicSharedMemorySize, sm1);
    cudaFuncSetAttribute(k2, cudaFuncAttributeMaxDynamicSharedMemorySize, sm2);
    cudaFuncSetAttribute(k3, cudaFuncAttributeMaxDynamicSharedMemorySize, sm3);

    k1<<<B_SZ, CONVT, sm1>>>(x, w1, b1, buf1);
    k2<<<B_SZ, CONVT, sm2>>>(buf1, w2, b2, buf2);
    k3<<<dim3(B_SZ, 2), CONVT, sm3>>>(buf2, w3, b3, buf3);

    prep_kernel<<<B_SZ, 256>>>(b_init_h, bih1, bhh1, b_init_h2);

    rnn_lin1_kernel<<<128, 256>>>(bih2, bhh2, w_fc, b_fc, b_lin1, pred);

    lin2_kernel<<<B_SZ, 384>>>(w_lin2, b_lin2, outc);

    (void)in_sizes; (void)n_in; (void)out_size;
}

// round 4
// speedup vs baseline: 1.5887x; 1.1453x over previous
#include <cuda_runtime.h>
#include <cuda_bf16.h>
#include <cstdint>

#define B_SZ 512
#define HID 256
#define TLEN 23
#define FLATN 5184

typedef unsigned long long ull;

// ---------------- scratch ----------------
__device__ float g_buf1[B_SZ * 12 * 36 * 3 * 16];   // conv1 out NDHWC
__device__ float g_buf2[B_SZ * 6 * 18 * 3 * 32];    // conv2 out NDHWC
__device__ float g_buf3[B_SZ * 3 * 9 * 3 * 64];     // conv3 out NDHWC == flat
__device__ float g_h[B_SZ * HID];
__device__ float g_h2[B_SZ * HID];
__device__ float g_ih[B_SZ * HID];
__device__ float g_t1[B_SZ * HID];

// conv weights transposed: wT[(ic*27 + kd*9 + kh*3 + kw)*OC + oc]
__device__ float g_wc1[162 * 16];
__device__ float g_wc2[432 * 32];
__device__ float g_wc3[864 * 64];

// matmul weights packed-transposed [k4][j]
__device__ ulonglong2 g_wt[3 * 64 * 256];
__device__ ulonglong2 g_wAq[16 * 256];
__device__ ulonglong2 g_wBq[16 * 256];
__device__ ulonglong2 g_wCq[64 * 256];
__device__ ulonglong2 g_wl1t[1296 * 256];

// ---------------- f32x2 helpers ----------------
__device__ __forceinline__ void fma2(ull& acc, ull a, ull b) {
    asm("fma.rn.f32x2 %0, %1, %2, %0;" : "+l"(acc) : "l"(a), "l"(b));
}
__device__ __forceinline__ ull pk2(float lo, float hi) {
    ull r; asm("mov.b64 %0, {%1,%2};" : "=l"(r) : "f"(lo), "f"(hi)); return r;
}
__device__ __forceinline__ ull dupf(float v) {
    ull r; asm("mov.b64 %0, {%1,%1};" : "=l"(r) : "f"(v)); return r;
}
__device__ __forceinline__ float2 upk(ull v) {
    float lo, hi; asm("mov.b64 {%0,%1}, %2;" : "=f"(lo), "=f"(hi) : "l"(v));
    return make_float2(lo, hi);
}

// ---------------- weight packers ----------------
__global__ __launch_bounds__(256) void pack_convw_kernel(
    const float* __restrict__ w1, const float* __restrict__ w2,
    const float* __restrict__ w3)
{
    const int idx = blockIdx.x * 256 + threadIdx.x;
    if (idx >= 71712) return;
    const float* src; float* dst; int OC, ICK, local;
    if (idx < 2592)       { local = idx;         src = w1; dst = g_wc1; OC = 16; ICK = 162; }
    else if (idx < 16416) { local = idx - 2592;  src = w2; dst = g_wc2; OC = 32; ICK = 432; }
    else                  { local = idx - 16416; src = w3; dst = g_wc3; OC = 64; ICK = 864; }
    const int oc = local % OC, k = local / OC;
    dst[local] = src[(size_t)oc * ICK + k];
}

__global__ __launch_bounds__(256) void pack_weights_kernel(
    const float* __restrict__ whh1, const float* __restrict__ wih2,
    const float* __restrict__ whh2, const float* __restrict__ w_init_h,
    const float* __restrict__ wih1, const float* __restrict__ w_init_h2,
    const float* __restrict__ w_lin1)
{
    const int idx = blockIdx.x * 256 + threadIdx.x;   // < 405504
    const float* src; ulonglong2* dst; int K; int local;
    if (idx < 49152)      { int m = idx / 16384; local = idx % 16384;
                            src = (m == 0) ? whh1 : ((m == 1) ? wih2 : whh2);
                            dst = g_wt + m * 16384; K = 256; }
    else if (idx < 53248) { local = idx - 49152; src = w_init_h;  dst = g_wAq;  K = 64; }
    else if (idx < 57344) { local = idx - 53248; src = wih1;      dst = g_wBq;  K = 64; }
    else if (idx < 73728) { local = idx - 57344; src = w_init_h2; dst = g_wCq;  K = 256; }
    else                  { local = idx - 73728; src = w_lin1;    dst = g_wl1t; K = 5184; }
    const int j = local % 256;
    const int k4 = local / 256;
    const float4 v = *(const float4*)&src[(size_t)j * K + k4 * 4];
    ulonglong2 o; o.x = pk2(v.x, v.y); o.y = pk2(v.z, v.w);
    dst[local] = o;
}

// ---------------------------------------------------------------------------
// conv accumulation for one item (oc, ph, pdb): all ic of one chunk.
// xs layout [ (d*H+h)*3+w ][ IC ]; ws layout [ icl*27 + kd*9+kh*3+kw ][ OC ].
// acc[p][ch][pw]: f32x2 over adjacent conv-d pair.
// ---------------------------------------------------------------------------
template <int IC, int OC, int D, int H, int WCH, bool SAFE>
__device__ __forceinline__ void conv_acc(
    const float* __restrict__ xs, const float* __restrict__ ws,
    int oc, int icbase, int pdb, int ph, bool dlo, bool dhi, ull acc[3][2][3])
{
    const int dsl = 6 * pdb - 1;
#pragma unroll 1
    for (int icl = 0; icl < WCH; icl++) {
        const float* xb = xs + icbase + icl;
        const float* wb = ws + icl * 27 * OC + oc;
#pragma unroll
        for (int hxr = 0; hxr < 4; hxr++) {
            const int hx = 2 * ph - 1 + hxr;
            const bool hok = SAFE || ((unsigned)hx < (unsigned)H);
            ull xq[3][7];
#pragma unroll
            for (int c = 0; c < 3; c++) {
                float xr[8];
#pragma unroll
                for (int i = 0; i < 8; i++) {
                    const int dx = dsl + i;
                    bool ok = hok;
                    if (i == 0) ok = ok && !dlo;
                    if (i == 7) ok = ok && !dhi;
                    xr[i] = ok ? xb[((dx * H + hx) * 3 + c) * IC] : 0.f;
                }
#pragma unroll
                for (int i = 0; i < 7; i++) xq[c][i] = pk2(xr[i], xr[i + 1]);
            }
#pragma unroll
            for (int ch = 0; ch < 2; ch++) {
                const int kh = hxr - ch;
                if (kh < 0 || kh > 2) continue;
#pragma unroll
                for (int kd = 0; kd < 3; kd++) {
                    const float* wp = wb + (kd * 9 + kh * 3) * OC;
                    const ull W0 = dupf(wp[0]);
                    const ull W1 = dupf(wp[OC]);
                    const ull W2 = dupf(wp[2 * OC]);
#pragma unroll
                    for (int p = 0; p < 3; p++) {
                        const int xi = 2 * p + kd;
                        fma2(acc[p][ch][0], W1, xq[0][xi]);
                        fma2(acc[p][ch][0], W2, xq[1][xi]);
                        fma2(acc[p][ch][1], W0, xq[0][xi]);
                        fma2(acc[p][ch][1], W1, xq[1][xi]);
                        fma2(acc[p][ch][1], W2, xq[2][xi]);
                        fma2(acc[p][ch][2], W0, xq[1][xi]);
                        fma2(acc[p][ch][2], W1, xq[2][xi]);
                    }
                }
            }
        }
    }
}

// ---------------------------------------------------------------------------
// conv3d(3x3x3,pad1)+bias+relu+maxpool(2,2,1). 576 = OC*H2 threads, NDHWC out.
// ---------------------------------------------------------------------------
template <int IC, int OC, int D, int H, int WCH, bool TRANSIN>
__global__ __launch_bounds__(576, 1) void conv_k(
    const float* __restrict__ x, const float* __restrict__ wT,
    const float* __restrict__ bias, float* __restrict__ out)
{
    constexpr int D2 = D / 2, H2 = H / 2, ND = D2 / 3;
    constexpr int SLAB = D * H * 3 * IC;
    constexpr int WSZ = WCH * 27 * OC;
    constexpr int NCH = IC / WCH;
    extern __shared__ float sm[];
    float* xs = sm;            // [D*H*3][IC]
    float* ws = sm + SLAB;     // [WCH*27][OC]

    const int b = blockIdx.x;
    const int tid = threadIdx.x;
    const int oc = tid % OC;
    const int ph = tid / OC;   // < H2

    if (TRANSIN) {
        const float* xb = x + (size_t)b * SLAB;
        for (int i = tid; i < SLAB; i += 576) {
            const int ic = i / (D * H * 3), s = i - ic * (D * H * 3);
            xs[s * IC + ic] = xb[i];
        }
    } else {
        const float4* src = (const float4*)(x + (size_t)b * SLAB);
        float4* dst = (float4*)xs;
        for (int i = tid; i < SLAB / 4; i += 576) dst[i] = src[i];
    }
    if (NCH == 1) {
        const float4* wsrc = (const float4*)wT;
        float4* wdst = (float4*)ws;
        for (int i = tid; i < WSZ / 4; i += 576) wdst[i] = wsrc[i];
    }
    __syncthreads();

    const bool hsafe = (ph > 0) && (ph < H2 - 1);
    const float bv = __ldg(&bias[oc]);

#pragma unroll 1
    for (int it = 0; it < ND; it++) {
        ull acc[3][2][3];
#pragma unroll
        for (int p = 0; p < 3; p++)
#pragma unroll
            for (int c = 0; c < 2; c++)
#pragma unroll
                for (int w = 0; w < 3; w++) acc[p][c][w] = 0ull;
        const bool dlo = (it == 0), dhi = (it == ND - 1);

#pragma unroll
        for (int ch = 0; ch < NCH; ch++) {
            if (NCH > 1) {
                __syncthreads();
                const float4* wsrc = (const float4*)(wT + (size_t)ch * WSZ);
                float4* wdst = (float4*)ws;
                for (int i = tid; i < WSZ / 4; i += 576) wdst[i] = wsrc[i];
                __syncthreads();
            }
            if (hsafe)
                conv_acc<IC, OC, D, H, WCH, true>(xs, ws, oc, ch * WCH, it, ph, dlo, dhi, acc);
            else
                conv_acc<IC, OC, D, H, WCH, false>(xs, ws, oc, ch * WCH, it, ph, dlo, dhi, acc);
        }

#pragma unroll
        for (int p = 0; p < 3; p++) {
            const int pd = it * 3 + p;
#pragma unroll
            for (int pw = 0; pw < 3; pw++) {
                const float2 u0 = upk(acc[p][0][pw]);
                const float2 u1 = upk(acc[p][1][pw]);
                float m = fmaxf(fmaxf(u0.x, u0.y), fmaxf(u1.x, u1.y)) + bv;
                out[((((size_t)b * D2 + pd) * H2 + ph) * 3 + pw) * OC + oc] = fmaxf(m, 0.f);
            }
        }
    }
}

// ---------------------------------------------------------------------------
// prep: mean over 81 positions -> h, ih_const, h2
// ---------------------------------------------------------------------------
__global__ __launch_bounds__(256) void prep_kernel(
    const float* __restrict__ b_init_h, const float* __restrict__ bih1,
    const float* __restrict__ bhh1, const float* __restrict__ b_init_h2)
{
    __shared__ __align__(16) float ms[64];
    __shared__ __align__(16) float hsh[256];
    const int b = blockIdx.x, j = threadIdx.x;
    if (j < 64) {
        float s = 0.f;
        const float* p = g_buf3 + (size_t)b * FLATN + j;
        for (int q = 0; q < 81; q++) s += p[q * 64];
        ms[j] = s * (1.f / 81.f);
    }
    __syncthreads();
    ull aA = 0ull, aB = 0ull;
#pragma unroll
    for (int k4 = 0; k4 < 16; k4++) {
        const ulonglong2 wa = g_wAq[k4 * 256 + j];
        const ulonglong2 wb = g_wBq[k4 * 256 + j];
        const ulonglong2 mv = *(const ulonglong2*)&ms[k4 * 4];
        fma2(aA, wa.x, mv.x); fma2(aA, wa.y, mv.y);
        fma2(aB, wb.x, mv.x); fma2(aB, wb.y, mv.y);
    }
    const float2 uA = upk(aA);
    const float2 uB = upk(aB);
    const float h = uA.x + uA.y + b_init_h[j];
    g_h[(size_t)b * HID + j] = h;
    g_ih[(size_t)b * HID + j] = uB.x + uB.y + bih1[j] + bhh1[j];
    hsh[j] = h;
    __syncthreads();
    ull aC = 0ull;
#pragma unroll 8
    for (int k4 = 0; k4 < 64; k4++) {
        const ulonglong2 wc = g_wCq[k4 * 256 + j];
        const ulonglong2 hv = *(const ulonglong2*)&hsh[k4 * 4];
        fma2(aC, wc.x, hv.x); fma2(aC, wc.y, hv.y);
    }
    const float2 uC = upk(aC);
    g_h2[(size_t)b * HID + j] = uC.x + uC.y + b_init_h2[j];
}

// ---------------------------------------------------------------------------
// blocks 0..63: 23-step RNN (8 rows each); blocks 64..127: lin1 (8 rows each).
// ---------------------------------------------------------------------------
#define RROWS 8
__global__ __launch_bounds__(256) void rnn_lin1_kernel(
    const float* __restrict__ bih2, const float* __restrict__ bhh2,
    const float* __restrict__ w_fc, const float* __restrict__ b_fc,
    const float* __restrict__ b_lin1, float* __restrict__ pred_out)
{
    __shared__ __align__(16) float sm[6400];
    const int j = threadIdx.x;

    if (blockIdx.x < 64) {
        float* h_s  = sm;
        float* h2_s = sm + 2048;
        float* ih_s = sm + 4096;
        float* red  = sm + 6144;
        const int r0 = blockIdx.x * RROWS;
        const int warp = j >> 5, lane = j & 31;
#pragma unroll
        for (int r = 0; r < RROWS; r++) {
            h_s[r * 256 + j]  = g_h[(size_t)(r0 + r) * HID + j];
            h2_s[r * 256 + j] = g_h2[(size_t)(r0 + r) * HID + j];
            ih_s[r * 256 + j] = g_ih[(size_t)(r0 + r) * HID + j];
        }
        const float bias2 = bih2[j] + bhh2[j];
        const float wf = w_fc[j];
        const float bfc = b_fc[0];
        __syncthreads();

        const ulonglong2* W1 = g_wt;
        const ulonglong2* W2 = g_wt + 16384;
        const ulonglong2* W3 = g_wt + 32768;

        for (int t = 0; t < TLEN; t++) {
            ull a1[RROWS];
#pragma unroll
            for (int r = 0; r < RROWS; r++) a1[r] = 0ull;
#pragma unroll 4
            for (int k4 = 0; k4 < 64; k4++) {
                const ulonglong2 wv = W1[k4 * 256 + j];
#pragma unroll
                for (int r = 0; r < RROWS; r++) {
                    const ulonglong2 hv = *(const ulonglong2*)&h_s[r * 256 + k4 * 4];
                    fma2(a1[r], wv.x, hv.x);
                    fma2(a1[r], wv.y, hv.y);
                }
            }
            float hn[RROWS];
#pragma unroll
            for (int r = 0; r < RROWS; r++) {
                const float2 u = upk(a1[r]);
                hn[r] = tanhf(ih_s[r * 256 + j] + u.x + u.y);
            }
            __syncthreads();
#pragma unroll
            for (int r = 0; r < RROWS; r++) h_s[r * 256 + j] = hn[r];
            __syncthreads();

            ull a2[RROWS];
#pragma unroll
            for (int r = 0; r < RROWS; r++) a2[r] = 0ull;
#pragma unroll 2
            for (int k4 = 0; k4 < 64; k4++) {
                const ulonglong2 wv2 = W2[k4 * 256 + j];
                const ulonglong2 wv3 = W3[k4 * 256 + j];
#pragma unroll
                for (int r = 0; r < RROWS; r++) {
                    const ulonglong2 hv = *(const ulonglong2*)&h_s[r * 256 + k4 * 4];
                    const ulonglong2 gv = *(const ulonglong2*)&h2_s[r * 256 + k4 * 4];
                    fma2(a2[r], wv2.x, hv.x);
                    fma2(a2[r], wv2.y, hv.y);
                    fma2(a2[r], wv3.x, gv.x);
                    fma2(a2[r], wv3.y, gv.y);
                }
            }
            float h2n[RROWS];
#pragma unroll
            for (int r = 0; r < RROWS; r++) {
                const float2 u = upk(a2[r]);
                h2n[r] = tanhf(bias2 + u.x + u.y);
            }
            __syncthreads();
#pragma unroll
            for (int r = 0; r < RROWS; r++) h2_s[r * 256 + j] = h2n[r];

#pragma unroll
            for (int r = 0; r < RROWS; r++) {
                float v = h2n[r] * wf;
                v += __shfl_down_sync(0xffffffffu, v, 16);
                v += __shfl_down_sync(0xffffffffu, v, 8);
                v += __shfl_down_sync(0xffffffffu, v, 4);
                v += __shfl_down_sync(0xffffffffu, v, 2);
                v += __shfl_down_sync(0xffffffffu, v, 1);
                if (lane == 0) red[warp * RROWS + r] = v;
            }
            __syncthreads();
            if (j < RROWS) {
                float s = bfc;
#pragma unroll
                for (int w = 0; w < 8; w++) s += red[w * RROWS + j];
                pred_out[(size_t)(r0 + j) * TLEN + t] = s;
            }
            __syncthreads();
        }
    } else {
        float* fs = sm;    // [8][648]
        const int r0 = (blockIdx.x - 64) * 8;
        ull acc[8];
#pragma unroll
        for (int r = 0; r < 8; r++) acc[r] = 0ull;

        for (int kb = 0; kb < FLATN; kb += 648) {
            __syncthreads();
#pragma unroll
            for (int r = 0; r < 8; r++)
                for (int k = j; k < 648; k += 256)
                    fs[r * 648 + k] = g_buf3[(size_t)(r0 + r) * FLATN + kb + k];
            __syncthreads();
            const int k4b = kb / 4;
#pragma unroll 2
            for (int k4 = 0; k4 < 162; k4++) {
                const ulonglong2 wv = g_wl1t[(k4b + k4) * 256 + j];
#pragma unroll
                for (int r = 0; r < 8; r++) {
                    const ulonglong2 hv = *(const ulonglong2*)&fs[r * 648 + k4 * 4];
                    fma2(acc[r], wv.x, hv.x);
                    fma2(acc[r], wv.y, hv.y);
                }
            }
        }
        const float bb = b_lin1[j];
#pragma unroll
        for (int r = 0; r < 8; r++) {
            const float2 u = upk(acc[r]);
            g_t1[(size_t)(r0 + r) * HID + j] = tanhf(u.x + u.y + bb);
        }
    }
}

__global__ __launch_bounds__(384) void lin2_kernel(
    const float* __restrict__ w_lin2, const float* __restrict__ b_lin2,
    float* __restrict__ outc)
{
    const int b = blockIdx.x;
    const int m = threadIdx.x >> 5;
    const int lane = threadIdx.x & 31;
    const float* tr = &g_t1[(size_t)b * HID];
    const float* wr = &w_lin2[(size_t)m * HID];
    float s = 0.f;
    for (int k = lane; k < HID; k += 32) s += tr[k] * wr[k];
    s += __shfl_down_sync(0xffffffffu, s, 16);
    s += __shfl_down_sync(0xffffffffu, s, 8);
    s += __shfl_down_sync(0xffffffffu, s, 4);
    s += __shfl_down_sync(0xffffffffu, s, 2);
    s += __shfl_down_sync(0xffffffffu, s, 1);
    if (lane == 0) outc[b * 12 + m] = s + b_lin2[m];
}

// ---------------------------------------------------------------------------

extern "C" void kernel_launch(void* const* d_in, const int* in_sizes, int n_in,
                              void* d_out, int out_size)
{
    const float* x        = (const float*)d_in[0];
    const float* w1       = (const float*)d_in[1];
    const float* b1       = (const float*)d_in[2];
    const float* w2       = (const float*)d_in[3];
    const float* b2       = (const float*)d_in[4];
    const float* w3       = (const float*)d_in[5];
    const float* b3       = (const float*)d_in[6];
    const float* wih1     = (const float*)d_in[7];
    const float* whh1     = (const float*)d_in[8];
    const float* bih1     = (const float*)d_in[9];
    const float* bhh1     = (const float*)d_in[10];
    const float* wih2     = (const float*)d_in[11];
    const float* whh2     = (const float*)d_in[12];
    const float* bih2     = (const float*)d_in[13];
    const float* bhh2     = (const float*)d_in[14];
    const float* w_init_h = (const float*)d_in[15];
    const float* b_init_h = (const float*)d_in[16];
    const float* w_init_h2= (const float*)d_in[17];
    const float* b_init_h2= (const float*)d_in[18];
    const float* w_fc     = (const float*)d_in[19];
    const float* b_fc     = (const float*)d_in[20];
    const float* w_lin1   = (const float*)d_in[21];
    const float* b_lin1   = (const float*)d_in[22];
    const float* w_lin2   = (const float*)d_in[23];
    const float* b_lin2   = (const float*)d_in[24];

    float* pred = (float*)d_out;
    float* outc = pred + B_SZ * TLEN;

    float *buf1, *buf2, *buf3, *wc1, *wc2, *wc3;
    cudaGetSymbolAddress((void**)&buf1, g_buf1);
    cudaGetSymbolAddress((void**)&buf2, g_buf2);
    cudaGetSymbolAddress((void**)&buf3, g_buf3);
    cudaGetSymbolAddress((void**)&wc1, g_wc1);
    cudaGetSymbolAddress((void**)&wc2, g_wc2);
    cudaGetSymbolAddress((void**)&wc3, g_wc3);

    pack_convw_kernel<<<281, 256>>>(w1, w2, w3);
    pack_weights_kernel<<<1584, 256>>>(whh1, wih2, whh2, w_init_h, wih1,
                                       w_init_h2, w_lin1);

    auto k1 = &conv_k<6, 16, 24, 72, 6, true>;    // smem 134784
    auto k2 = &conv_k<16, 32, 12, 36, 16, false>; // smem 138240
    auto k3 = &conv_k<32, 64, 6, 18, 16, false>;  // smem 152064
    const int sm1 = (24 * 72 * 3 * 6 + 6 * 27 * 16) * 4;
    const int sm2 = (12 * 36 * 3 * 16 + 16 * 27 * 32) * 4;
    const int sm3 = (6 * 18 * 3 * 32 + 16 * 27 * 64) * 4;
    cudaFuncSetAttribute(k1, cudaFuncAttributeMaxDynamicSharedMemorySize, sm1);
    cudaFuncSetAttribute(k2, cudaFuncAttributeMaxDynamicSharedMemorySize, sm2);
    cudaFuncSetAttribute(k3, cudaFuncAttributeMaxDynamicSharedMemorySize, sm3);

    k1<<<B_SZ, 576, sm1>>>(x, wc1, b1, buf1);
    k2<<<B_SZ, 576, sm2>>>(buf1, wc2, b2, buf2);
    k3<<<B_SZ, 576, sm3>>>(buf2, wc3, b3, buf3);

    prep_kernel<<<B_SZ, 256>>>(b_init_h, bih1, bhh1, b_init_h2);
    rnn_lin1_kernel<<<128, 256>>>(bih2, bhh2, w_fc, b_fc, b_lin1, pred);
    lin2_kernel<<<B_SZ, 384>>>(w_lin2, b_lin2, outc);

    (void)in_sizes; (void)n_in; (void)out_size;
}

// round 6
// speedup vs baseline: 1.6032x; 1.0091x over previous
#include <cuda_runtime.h>
#include <cuda_bf16.h>
#include <cstdint>

#define B_SZ 512
#define HID 256
#define TLEN 23
#define FLATN 5184

typedef unsigned long long ull;

// ---------------- scratch ----------------
__device__ float g_buf1[B_SZ * 12 * 36 * 3 * 16];   // conv1 out NDHWC
__device__ float g_buf2[B_SZ * 6 * 18 * 3 * 32];    // conv2 out NDHWC
__device__ float g_buf3[B_SZ * 3 * 9 * 3 * 64];     // conv3 out NDHWC == flat
__device__ float g_h[B_SZ * HID];
__device__ float g_h2[B_SZ * HID];
__device__ float g_ih[B_SZ * HID];
__device__ float g_t1[B_SZ * HID];

// conv weights transposed + f32x2-dup'd: wd[(ic*27 + kd*9+kh*3+kw)*OC + oc]
__device__ ull g_wc1[162 * 16];
__device__ ull g_wc2[432 * 32];
__device__ ull g_wc3[864 * 64];

// matmul weights packed-transposed [k4][j]
__device__ ulonglong2 g_wt[3 * 64 * 256];
__device__ ulonglong2 g_wAq[16 * 256];
__device__ ulonglong2 g_wBq[16 * 256];
__device__ ulonglong2 g_wCq[64 * 256];
__device__ ulonglong2 g_wl1t[1296 * 256];

// ---------------- f32x2 helpers ----------------
__device__ __forceinline__ void fma2(ull& acc, ull a, ull b) {
    asm("fma.rn.f32x2 %0, %1, %2, %0;" : "+l"(acc) : "l"(a), "l"(b));
}
__device__ __forceinline__ ull pk2(float lo, float hi) {
    ull r; asm("mov.b64 %0, {%1,%2};" : "=l"(r) : "f"(lo), "f"(hi)); return r;
}
__device__ __forceinline__ float2 upk(ull v) {
    float lo, hi; asm("mov.b64 {%0,%1}, %2;" : "=f"(lo), "=f"(hi) : "l"(v));
    return make_float2(lo, hi);
}

// ---------------- weight packers ----------------
__global__ __launch_bounds__(256) void pack_convw_kernel(
    const float* __restrict__ w1, const float* __restrict__ w2,
    const float* __restrict__ w3)
{
    const int idx = blockIdx.x * 256 + threadIdx.x;
    if (idx >= 71712) return;
    const float* src; ull* dst; int OC, ICK, local;
    if (idx < 2592)       { local = idx;         src = w1; dst = g_wc1; OC = 16; ICK = 162; }
    else if (idx < 16416) { local = idx - 2592;  src = w2; dst = g_wc2; OC = 32; ICK = 432; }
    else                  { local = idx - 16416; src = w3; dst = g_wc3; OC = 64; ICK = 864; }
    const int oc = local % OC, k = local / OC;
    const float v = src[(size_t)oc * ICK + k];
    dst[local] = pk2(v, v);
}

__global__ __launch_bounds__(256) void pack_weights_kernel(
    const float* __restrict__ whh1, const float* __restrict__ wih2,
    const float* __restrict__ whh2, const float* __restrict__ w_init_h,
    const float* __restrict__ wih1, const float* __restrict__ w_init_h2,
    const float* __restrict__ w_lin1)
{
    const int idx = blockIdx.x * 256 + threadIdx.x;   // < 405504
    const float* src; ulonglong2* dst; int K; int local;
    if (idx < 49152)      { int m = idx / 16384; local = idx % 16384;
                            src = (m == 0) ? whh1 : ((m == 1) ? wih2 : whh2);
                            dst = g_wt + m * 16384; K = 256; }
    else if (idx < 53248) { local = idx - 49152; src = w_init_h;  dst = g_wAq;  K = 64; }
    else if (idx < 57344) { local = idx - 53248; src = wih1;      dst = g_wBq;  K = 64; }
    else if (idx < 73728) { local = idx - 57344; src = w_init_h2; dst = g_wCq;  K = 256; }
    else                  { local = idx - 73728; src = w_lin1;    dst = g_wl1t; K = 5184; }
    const int j = local % 256;
    const int k4 = local / 256;
    const float4 v = *(const float4*)&src[(size_t)j * K + k4 * 4];
    ulonglong2 o; o.x = pk2(v.x, v.y); o.y = pk2(v.z, v.w);
    dst[local] = o;
}

// ---------------------------------------------------------------------------
// conv accumulation for one item (oc, ph) over one ic chunk.
// xs layout [ (dloc*H+h)*3+w ][ IC ] ; ws (ull, dup'd) [ icl*27 + ... ][ OC ].
// ---------------------------------------------------------------------------
template <int IC, int OC, int DSLAB, int H, int WCH, bool SAFE>
__device__ __forceinline__ void conv_acc(
    const float* __restrict__ xs, const ull* __restrict__ ws,
    int oc, int icbase, int dsl, int ph, bool dlo, bool dhi, ull acc[3][2][3])
{
#pragma unroll 1
    for (int icl = 0; icl < WCH; icl++) {
        const float* xb = xs + icbase + icl;
        const ull* wb = ws + icl * 27 * OC + oc;
#pragma unroll
        for (int hxr = 0; hxr < 4; hxr++) {
            const int hx = 2 * ph - 1 + hxr;
            const bool hok = SAFE || ((unsigned)hx < (unsigned)H);
            ull xq[3][7];
#pragma unroll
            for (int c = 0; c < 3; c++) {
                float xr[8];
#pragma unroll
                for (int i = 0; i < 8; i++) {
                    bool ok = hok;
                    if (i == 0) ok = ok && !dlo;
                    if (i == 7) ok = ok && !dhi;
                    xr[i] = ok ? xb[(((dsl + i) * H + hx) * 3 + c) * IC] : 0.f;
                }
#pragma unroll
                for (int i = 0; i < 7; i++) xq[c][i] = pk2(xr[i], xr[i + 1]);
            }
#pragma unroll
            for (int ch = 0; ch < 2; ch++) {
                const int kh = hxr - ch;
                if (kh < 0 || kh > 2) continue;
#pragma unroll
                for (int kd = 0; kd < 3; kd++) {
                    const ull* wp = wb + (kd * 9 + kh * 3) * OC;
                    const ull W0 = wp[0];
                    const ull W1 = wp[OC];
                    const ull W2 = wp[2 * OC];
#pragma unroll
                    for (int p = 0; p < 3; p++) {
                        const int xi = 2 * p + kd;
                        fma2(acc[p][ch][0], W1, xq[0][xi]);
                        fma2(acc[p][ch][0], W2, xq[1][xi]);
                        fma2(acc[p][ch][1], W0, xq[0][xi]);
                        fma2(acc[p][ch][1], W1, xq[1][xi]);
                        fma2(acc[p][ch][1], W2, xq[2][xi]);
                        fma2(acc[p][ch][2], W0, xq[1][xi]);
                        fma2(acc[p][ch][2], W1, xq[2][xi]);
                    }
                }
            }
        }
    }
}

// ---------------------------------------------------------------------------
// conv3d(3x3x3,pad1)+bias+relu+maxpool(2,2,1). 576 = OC*H2 threads, NDHWC out.
// SPLIT: blockIdx.y = D-half; slab covers DSLAB = 6*NDH+1 conv-d rows.
// ---------------------------------------------------------------------------
template <int IC, int OC, int D, int H, int WCH, int NDH, bool TRANSIN, bool SPLIT>
__global__ __launch_bounds__(576, 1) void conv_k(
    const float* __restrict__ x, const ull* __restrict__ wT,
    const float* __restrict__ bias, float* __restrict__ out)
{
    constexpr int H2 = H / 2;
    constexpr int D2 = D / 2;
    constexpr int DSLAB = SPLIT ? (6 * NDH + 1) : D;
    constexpr int SLAB = DSLAB * H * 3 * IC;
    constexpr int WSZ = WCH * 27 * OC;       // ull count
    constexpr int NCH = IC / WCH;
    extern __shared__ float sm[];
    float* xs = sm;                          // SLAB floats
    ull* ws = (ull*)(sm + SLAB);             // WSZ ulls

    const int b = blockIdx.x;
    const int half = SPLIT ? blockIdx.y : 0;
    const int dbase = SPLIT ? half * (6 * NDH - 1) : 0;
    const int tid = threadIdx.x;
    const int oc = tid % OC;
    const int ph = tid / OC;

    if (TRANSIN) {
        const float* xb = x + (size_t)b * IC * D * H * 3;
        for (int i = tid; i < SLAB; i += 576) {
            const int ic = i / (DSLAB * H * 3), s = i - ic * (DSLAB * H * 3);
            xs[s * IC + ic] = xb[ic * D * H * 3 + dbase * H * 3 + s];
        }
    } else {
        const float4* src = (const float4*)(x + ((size_t)b * D + dbase) * H * 3 * IC);
        float4* dst = (float4*)xs;
        for (int i = tid; i < SLAB / 4; i += 576) dst[i] = src[i];
    }
    if (NCH == 1) {
        const ulonglong2* wsrc = (const ulonglong2*)wT;
        ulonglong2* wdst = (ulonglong2*)ws;
        for (int i = tid; i < WSZ / 2; i += 576) wdst[i] = wsrc[i];
    }
    __syncthreads();

    const bool hsafe = (ph > 0) && (ph < H2 - 1);
    const float bv = __ldg(&bias[oc]);

#pragma unroll 1
    for (int pdb = 0; pdb < NDH; pdb++) {
        ull acc[3][2][3];
#pragma unroll
        for (int p = 0; p < 3; p++)
#pragma unroll
            for (int c = 0; c < 2; c++)
#pragma unroll
                for (int w = 0; w < 3; w++) acc[p][c][w] = 0ull;

        const bool dlo = (half == 0) && (pdb == 0);
        const bool dhi = (!SPLIT || half == 1) && (pdb == NDH - 1);
        const int dsl = 6 * pdb - 1 + half;   // local slab coordinate

#pragma unroll
        for (int ch = 0; ch < NCH; ch++) {
            if (NCH > 1) {
                __syncthreads();
                const ulonglong2* wsrc = (const ulonglong2*)(wT + (size_t)ch * WSZ);
                ulonglong2* wdst = (ulonglong2*)ws;
                for (int i = tid; i < WSZ / 2; i += 576) wdst[i] = wsrc[i];
                __syncthreads();
            }
            if (hsafe)
                conv_acc<IC, OC, DSLAB, H, WCH, true>(xs, ws, oc, ch * WCH, dsl, ph, dlo, dhi, acc);
            else
                conv_acc<IC, OC, DSLAB, H, WCH, false>(xs, ws, oc, ch * WCH, dsl, ph, dlo, dhi, acc);
        }

#pragma unroll
        for (int p = 0; p < 3; p++) {
            const int pd = (half * NDH + pdb) * 3 + p;
#pragma unroll
            for (int pw = 0; pw < 3; pw++) {
                const float2 u0 = upk(acc[p][0][pw]);
                const float2 u1 = upk(acc[p][1][pw]);
                float m = fmaxf(fmaxf(u0.x, u0.y), fmaxf(u1.x, u1.y)) + bv;
                out[((((size_t)b * D2 + pd) * H2 + ph) * 3 + pw) * OC + oc] = fmaxf(m, 0.f);
            }
        }
    }
}

// ---------------------------------------------------------------------------
// prep: mean over 81 positions -> h, ih_const, h2
// ---------------------------------------------------------------------------
__global__ __launch_bounds__(256) void prep_kernel(
    const float* __restrict__ b_init_h, const float* __restrict__ bih1,
    const float* __restrict__ bhh1, const float* __restrict__ b_init_h2)
{
    __shared__ __align__(16) float ms[64];
    __shared__ __align__(16) float hsh[256];
    const int b = blockIdx.x, j = threadIdx.x;
    if (j < 64) {
        float s = 0.f;
        const float* p = g_buf3 + (size_t)b * FLATN + j;
        for (int q = 0; q < 81; q++) s += p[q * 64];
        ms[j] = s * (1.f / 81.f);
    }
    __syncthreads();
    ull aA = 0ull, aB = 0ull;
#pragma unroll
    for (int k4 = 0; k4 < 16; k4++) {
        const ulonglong2 wa = g_wAq[k4 * 256 + j];
        const ulonglong2 wb = g_wBq[k4 * 256 + j];
        const ulonglong2 mv = *(const ulonglong2*)&ms[k4 * 4];
        fma2(aA, wa.x, mv.x); fma2(aA, wa.y, mv.y);
        fma2(aB, wb.x, mv.x); fma2(aB, wb.y, mv.y);
    }
    const float2 uA = upk(aA);
    const float2 uB = upk(aB);
    const float h = uA.x + uA.y + b_init_h[j];
    g_h[(size_t)b * HID + j] = h;
    g_ih[(size_t)b * HID + j] = uB.x + uB.y + bih1[j] + bhh1[j];
    hsh[j] = h;
    __syncthreads();
    ull aC = 0ull;
#pragma unroll 8
    for (int k4 = 0; k4 < 64; k4++) {
        const ulonglong2 wc = g_wCq[k4 * 256 + j];
        const ulonglong2 hv = *(const ulonglong2*)&hsh[k4 * 4];
        fma2(aC, wc.x, hv.x); fma2(aC, wc.y, hv.y);
    }
    const float2 uC = upk(aC);
    g_h2[(size_t)b * HID + j] = uC.x + uC.y + b_init_h2[j];
}

// ---------------------------------------------------------------------------
// 512 threads/block. Blocks 0..63: RNN, 8 rows (two independent 4-row groups).
// Blocks 64..127: lin1, 8 rows (two 4-row groups). Weight lines shared in L1.
// ---------------------------------------------------------------------------
__global__ __launch_bounds__(512) void rnn_lin1_kernel(
    const float* __restrict__ bih2, const float* __restrict__ bhh2,
    const float* __restrict__ w_fc, const float* __restrict__ b_fc,
    const float* __restrict__ b_lin1, float* __restrict__ pred_out)
{
    __shared__ __align__(16) float sm[6400];
    const int tid = threadIdx.x;
    const int rg = tid >> 8;          // row group 0/1
    const int j = tid & 255;

    if (blockIdx.x < 64) {
        float* h_s  = sm;             // [8][256]
        float* h2_s = sm + 2048;
        float* ih_s = sm + 4096;
        float* red  = sm + 6144;      // [16 warps][4 rows]
        const int r0 = blockIdx.x * 8;
        const int warp = tid >> 5, lane = tid & 31;

#pragma unroll
        for (int r = 0; r < 4; r++) {
            const int row = rg * 4 + r;
            h_s[row * 256 + j]  = g_h[(size_t)(r0 + row) * HID + j];
            h2_s[row * 256 + j] = g_h2[(size_t)(r0 + row) * HID + j];
            ih_s[row * 256 + j] = g_ih[(size_t)(r0 + row) * HID + j];
        }
        const float bias2 = bih2[j] + bhh2[j];
        const float wf = w_fc[j];
        const float bfc = b_fc[0];
        __syncthreads();

        const ulonglong2* W1 = g_wt;
        const ulonglong2* W2 = g_wt + 16384;
        const ulonglong2* W3 = g_wt + 32768;

        for (int t = 0; t < TLEN; t++) {
            ull a1[4];
#pragma unroll
            for (int r = 0; r < 4; r++) a1[r] = 0ull;
#pragma unroll 4
            for (int k4 = 0; k4 < 64; k4++) {
                const ulonglong2 wv = W1[k4 * 256 + j];
#pragma unroll
                for (int r = 0; r < 4; r++) {
                    const ulonglong2 hv = *(const ulonglong2*)&h_s[(rg * 4 + r) * 256 + k4 * 4];
                    fma2(a1[r], wv.x, hv.x);
                    fma2(a1[r], wv.y, hv.y);
                }
            }
            float hn[4];
#pragma unroll
            for (int r = 0; r < 4; r++) {
                const float2 u = upk(a1[r]);
                hn[r] = tanhf(ih_s[(rg * 4 + r) * 256 + j] + u.x + u.y);
            }
            __syncthreads();
#pragma unroll
            for (int r = 0; r < 4; r++) h_s[(rg * 4 + r) * 256 + j] = hn[r];
            __syncthreads();

            ull a2[4];
#pragma unroll
            for (int r = 0; r < 4; r++) a2[r] = 0ull;
#pragma unroll 2
            for (int k4 = 0; k4 < 64; k4++) {
                const ulonglong2 wv2 = W2[k4 * 256 + j];
                const ulonglong2 wv3 = W3[k4 * 256 + j];
#pragma unroll
                for (int r = 0; r < 4; r++) {
                    const ulonglong2 hv = *(const ulonglong2*)&h_s[(rg * 4 + r) * 256 + k4 * 4];
                    const ulonglong2 gv = *(const ulonglong2*)&h2_s[(rg * 4 + r) * 256 + k4 * 4];
                    fma2(a2[r], wv2.x, hv.x);
                    fma2(a2[r], wv2.y, hv.y);
                    fma2(a2[r], wv3.x, gv.x);
                    fma2(a2[r], wv3.y, gv.y);
                }
            }
            float h2n[4];
#pragma unroll
            for (int r = 0; r < 4; r++) {
                const float2 u = upk(a2[r]);
                h2n[r] = tanhf(bias2 + u.x + u.y);
            }
            __syncthreads();
#pragma unroll
            for (int r = 0; r < 4; r++) h2_s[(rg * 4 + r) * 256 + j] = h2n[r];

#pragma unroll
            for (int r = 0; r < 4; r++) {
                float v = h2n[r] * wf;
                v += __shfl_down_sync(0xffffffffu, v, 16);
                v += __shfl_down_sync(0xffffffffu, v, 8);
                v += __shfl_down_sync(0xffffffffu, v, 4);
                v += __shfl_down_sync(0xffffffffu, v, 2);
                v += __shfl_down_sync(0xffffffffu, v, 1);
                if (lane == 0) red[warp * 4 + r] = v;
            }
            __syncthreads();
            if (tid < 8) {
                const int g = tid >> 2;
                float s = bfc;
#pragma unroll
                for (int w = 0; w < 8; w++) s += red[((g << 3) + w) * 4 + (tid & 3)];
                pred_out[(size_t)(r0 + tid) * TLEN + t] = s;
            }
            __syncthreads();
        }
    } else {
        float* fs = sm;    // [8][648]
        const int r0 = (blockIdx.x - 64) * 8;
        ull acc[4];
#pragma unroll
        for (int r = 0; r < 4; r++) acc[r] = 0ull;

        for (int kb = 0; kb < FLATN; kb += 648) {
            __syncthreads();
            for (int i = tid; i < 8 * 648; i += 512) {
                const int r = i / 648, k = i - r * 648;
                fs[i] = g_buf3[(size_t)(r0 + r) * FLATN + kb + k];
            }
            __syncthreads();
            const int k4b = kb / 4;
#pragma unroll 2
            for (int k4 = 0; k4 < 162; k4++) {
                const ulonglong2 wv = g_wl1t[(k4b + k4) * 256 + j];
#pragma unroll
                for (int r = 0; r < 4; r++) {
                    const ulonglong2 hv = *(const ulonglong2*)&fs[(rg * 4 + r) * 648 + k4 * 4];
                    fma2(acc[r], wv.x, hv.x);
                    fma2(acc[r], wv.y, hv.y);
                }
            }
        }
        const float bb = b_lin1[j];
#pragma unroll
        for (int r = 0; r < 4; r++) {
            const float2 u = upk(acc[r]);
            g_t1[(size_t)(r0 + rg * 4 + r) * HID + j] = tanhf(u.x + u.y + bb);
        }
    }
}

__global__ __launch_bounds__(384) void lin2_kernel(
    const float* __restrict__ w_lin2, const float* __restrict__ b_lin2,
    float* __restrict__ outc)
{
    const int b = blockIdx.x;
    const int m = threadIdx.x >> 5;
    const int lane = threadIdx.x & 31;
    const float* tr = &g_t1[(size_t)b * HID];
    const float* wr = &w_lin2[(size_t)m * HID];
    float s = 0.f;
    for (int k = lane; k < HID; k += 32) s += tr[k] * wr[k];
    s += __shfl_down_sync(0xffffffffu, s, 16);
    s += __shfl_down_sync(0xffffffffu, s, 8);
    s += __shfl_down_sync(0xffffffffu, s, 4);
    s += __shfl_down_sync(0xffffffffu, s, 2);
    s += __shfl_down_sync(0xffffffffu, s, 1);
    if (lane == 0) outc[b * 12 + m] = s + b_lin2[m];
}

// ---------------------------------------------------------------------------

extern "C" void kernel_launch(void* const* d_in, const int* in_sizes, int n_in,
                              void* d_out, int out_size)
{
    const float* x        = (const float*)d_in[0];
    const float* w1       = (const float*)d_in[1];
    const float* b1       = (const float*)d_in[2];
    const float* w2       = (const float*)d_in[3];
    const float* b2       = (const float*)d_in[4];
    const float* w3       = (const float*)d_in[5];
    const float* b3       = (const float*)d_in[6];
    const float* wih1     = (const float*)d_in[7];
    const float* whh1     = (const float*)d_in[8];
    const float* bih1     = (const float*)d_in[9];
    const float* bhh1     = (const float*)d_in[10];
    const float* wih2     = (const float*)d_in[11];
    const float* whh2     = (const float*)d_in[12];
    const float* bih2     = (const float*)d_in[13];
    const float* bhh2     = (const float*)d_in[14];
    const float* w_init_h = (const float*)d_in[15];
    const float* b_init_h = (const float*)d_in[16];
    const float* w_init_h2= (const float*)d_in[17];
    const float* b_init_h2= (const float*)d_in[18];
    const float* w_fc     = (const float*)d_in[19];
    const float* b_fc     = (const float*)d_in[20];
    const float* w_lin1   = (const float*)d_in[21];
    const float* b_lin1   = (const float*)d_in[22];
    const float* w_lin2   = (const float*)d_in[23];
    const float* b_lin2   = (const float*)d_in[24];

    float* pred = (float*)d_out;
    float* outc = pred + B_SZ * TLEN;

    float *buf1, *buf2, *buf3;
    ull *wc1, *wc2, *wc3;
    cudaGetSymbolAddress((void**)&buf1, g_buf1);
    cudaGetSymbolAddress((void**)&buf2, g_buf2);
    cudaGetSymbolAddress((void**)&buf3, g_buf3);
    cudaGetSymbolAddress((void**)&wc1, g_wc1);
    cudaGetSymbolAddress((void**)&wc2, g_wc2);
    cudaGetSymbolAddress((void**)&wc3, g_wc3);

    pack_convw_kernel<<<281, 256>>>(w1, w2, w3);
    pack_weights_kernel<<<1584, 256>>>(whh1, wih2, whh2, w_init_h, wih1,
                                       w_init_h2, w_lin1);

    // conv1: D=24 split in 2 halves (NDH=2, DSLAB=13); conv2: split (NDH=1,
    // DSLAB=7); conv3: unsplit, 4 weight chunks.
    auto k1 = &conv_k<6, 16, 24, 72, 6, 2, true, true>;
    auto k2 = &conv_k<16, 32, 12, 36, 16, 1, false, true>;
    auto k3 = &conv_k<32, 64, 6, 18, 8, 1, false, false>;
    const int sm1 = 13 * 72 * 3 * 6 * 4 + 6 * 27 * 16 * 8;     // 88128
    const int sm2 = 7 * 36 * 3 * 16 * 4 + 16 * 27 * 32 * 8;    // 158976
    const int sm3 = 6 * 18 * 3 * 32 * 4 + 8 * 27 * 64 * 8;     // 152064
    cudaFuncSetAttribute(k1, cudaFuncAttributeMaxDynamicSharedMemorySize, sm1);
    cudaFuncSetAttribute(k2, cudaFuncAttributeMaxDynamicSharedMemorySize, sm2);
    cudaFuncSetAttribute(k3, cudaFuncAttributeMaxDynamicSharedMemorySize, sm3);

    k1<<<dim3(B_SZ, 2), 576, sm1>>>(x, wc1, b1, buf1);
    k2<<<dim3(B_SZ, 2), 576, sm2>>>(buf1, wc2, b2, buf2);
    k3<<<dim3(B_SZ, 1), 576, sm3>>>(buf2, wc3, b3, buf3);

    prep_kernel<<<B_SZ, 256>>>(b_init_h, bih1, bhh1, b_init_h2);
    rnn_lin1_kernel<<<128, 512>>>(bih2, bhh2, w_fc, b_fc, b_lin1, pred);
    lin2_kernel<<<B_SZ, 384>>>(w_lin2, b_lin2, outc);

    (void)in_sizes; (void)n_in; (void)out_size;
}